// round 1
// baseline (speedup 1.0000x reference)
#include <cuda_runtime.h>
#include <cstdint>
#include <cstddef>

#define Nn 20000
#define Ee 320000
#define Ff 128
#define Hh 8
#define EFe 64
#define Aa 128
#define Gg 32
#define F2 256

// ---------------- scratch (device globals; no allocations allowed) ----------------
__device__ float g_sb_mix[Gg * F2];
__device__ float g_sb_mlp[Gg * F2];
__device__ float g_hsrc[(size_t)Nn * Ff];
__device__ float g_hdst[(size_t)Nn * Ff];
__device__ float g_v[(size_t)Ee * Ff];      // per-edge values (164 MB)
__device__ float g_w[(size_t)Ee * Hh];      // per-edge logits, then exp(w - max)
__device__ float g_wmax[Nn * Hh];
__device__ float g_wsum[Nn * Hh];
__device__ float g_o[(size_t)Nn * Ff];
__device__ float g_hmid[(size_t)Nn * Ff];
__device__ float g_xn[(size_t)Nn * Ff];

__device__ __forceinline__ float siluf(float x) { return x / (1.f + __expf(-x)); }

// float atomic max via signed/unsigned monotone trick (init must be -inf)
__device__ __forceinline__ void atomicMaxF(float* addr, float v) {
    if (v >= 0.f) atomicMax((int*)addr, __float_as_int(v));
    else          atomicMin((unsigned int*)addr, __float_as_uint(v));
}

// ---------------- init: zero accumulators, -inf maxes (re-run every launch) -------
__global__ void k_init() {
    int i = blockIdx.x * 256 + threadIdx.x;
    if (i < Nn * Ff) g_o[i] = 0.f;
    if (i < Nn * Hh) { g_wmax[i] = __int_as_float(0xff800000); g_wsum[i] = 0.f; }
}

// ---------------- cond GEMMs: sb = cond @ w + b for mix and mlp -------------------
__global__ __launch_bounds__(256) void k_cond(const float* __restrict__ cond,
                                              const float* __restrict__ w_mix,
                                              const float* __restrict__ b_mix,
                                              const float* __restrict__ w_mlp,
                                              const float* __restrict__ b_mlp) {
    __shared__ float cs[Aa];
    int g = blockIdx.x;
    int which = blockIdx.y;
    const float* w = which ? w_mlp : w_mix;
    const float* b = which ? b_mlp : b_mix;
    float* outp = which ? g_sb_mlp : g_sb_mix;
    int t = threadIdx.x;
    if (t < Aa) cs[t] = cond[g * Aa + t];
    __syncthreads();
    float acc = b[t];
    #pragma unroll 8
    for (int k = 0; k < Aa; k++) acc = fmaf(cs[k], w[k * F2 + t], acc);
    outp[g * F2 + t] = acc;
}

// ---------------- node kernel 1: ada_ln(mix) + hh = x @ w_h + b_h -----------------
__global__ __launch_bounds__(256) void k_node1(const float* __restrict__ input,
                                               const int* __restrict__ batch,
                                               const float* __restrict__ w_h,
                                               const float* __restrict__ b_h) {
    extern __shared__ float sm[];
    float* w_s  = sm;              // 128*256
    float* xm_s = sm + Ff * F2;    // 32*136 (padded)
    const int tid = threadIdx.x;
    const int warp = tid >> 5, lane = tid & 31;
    const int nb = blockIdx.x * 32;

    {
        const float4* ws = (const float4*)w_h;
        float4* wd = (float4*)w_s;
        for (int i = tid; i < Ff * F2 / 4; i += 256) wd[i] = ws[i];
    }
    #pragma unroll
    for (int q = 0; q < 4; q++) {
        int r = warp * 4 + q;
        int n = nb + r;
        float4 x = ((const float4*)(input + (size_t)n * Ff))[lane];
        float s  = x.x + x.y + x.z + x.w;
        float ss = fmaf(x.x, x.x, fmaf(x.y, x.y, fmaf(x.z, x.z, x.w * x.w)));
        #pragma unroll
        for (int o = 16; o > 0; o >>= 1) {
            s  += __shfl_xor_sync(0xffffffffu, s, o);
            ss += __shfl_xor_sync(0xffffffffu, ss, o);
        }
        float mu = s * (1.f / Ff);
        float rstd = rsqrtf(ss * (1.f / Ff) - mu * mu + 1e-5f);
        int bix = batch[n];
        const float* sb = g_sb_mix + bix * F2;
        float4 sc = *((const float4*)(sb + lane * 4));
        float4 sh = *((const float4*)(sb + Ff + lane * 4));
        float4 o4;
        o4.x = (x.x - mu) * rstd * (1.f + sc.x) + sh.x;
        o4.y = (x.y - mu) * rstd * (1.f + sc.y) + sh.y;
        o4.z = (x.z - mu) * rstd * (1.f + sc.z) + sh.z;
        o4.w = (x.w - mu) * rstd * (1.f + sc.w) + sh.w;
        ((float4*)(xm_s + r * 136))[lane] = o4;
    }
    __syncthreads();

    float acc[4][8];
    #pragma unroll
    for (int i = 0; i < 4; i++)
        #pragma unroll
        for (int j = 0; j < 8; j++) acc[i][j] = 0.f;

    #pragma unroll 4
    for (int k = 0; k < Ff; k++) {
        float xa[4];
        #pragma unroll
        for (int i = 0; i < 4; i++) xa[i] = xm_s[(warp * 4 + i) * 136 + k];
        #pragma unroll
        for (int j = 0; j < 8; j++) {
            float wv = w_s[k * F2 + lane + 32 * j];
            #pragma unroll
            for (int i = 0; i < 4; i++) acc[i][j] = fmaf(xa[i], wv, acc[i][j]);
        }
    }
    #pragma unroll
    for (int j = 0; j < 8; j++) {
        int c = lane + 32 * j;
        float bb = __ldg(b_h + c);
        #pragma unroll
        for (int i = 0; i < 4; i++) {
            int n = nb + warp * 4 + i;
            float v = acc[i][j] + bb;
            if (c < Ff) g_hsrc[(size_t)n * Ff + c] = v;
            else        g_hdst[(size_t)n * Ff + (c - Ff)] = v;
        }
    }
}

// ---------------- edge kernel: LN(a), GEMM 64->128 + gathers + silu, GEMM 128->200 -
__global__ __launch_bounds__(256) void k_edge(const float* __restrict__ ain,
                                              const int* __restrict__ edges,
                                              const float* __restrict__ w_a,
                                              const float* __restrict__ w_vatt,
                                              const float* __restrict__ w_edge,
                                              const float* __restrict__ gain_e,
                                              const float* __restrict__ bias_e,
                                              const float* __restrict__ b_edge,
                                              float* __restrict__ aout) {
    extern __shared__ float sm[];
    float* wa_s = sm;                         // 64*128
    float* wc_s = wa_s + EFe * Ff;            // 128*224 (cols 0..135 w_vatt, 136..199 w_edge, rest 0)
    float* a_s  = wc_s + Ff * 224;            // 32*64
    float* an_s = a_s + 32 * EFe;             // 32*64
    float* m_s  = an_s + 32 * EFe;            // 32*136
    float* ge_s = m_s + 32 * 136;             // 64
    float* be_s = ge_s + EFe;                 // 64
    float* bd_s = be_s + EFe;                 // 64
    int*   src_s = (int*)(bd_s + EFe);        // 32
    int*   dst_s = src_s + 32;                // 32
    const int tid = threadIdx.x;
    const int warp = tid >> 5, lane = tid & 31;

    for (int i = tid; i < EFe * Ff; i += 256) wa_s[i] = w_a[i];
    for (int i = tid; i < Ff * 224; i += 256) {
        int k = i / 224, c = i - k * 224;
        float v = 0.f;
        if (c < 136)      v = w_vatt[k * 136 + c];
        else if (c < 200) v = w_edge[k * EFe + (c - 136)];
        wc_s[i] = v;
    }
    if (tid < EFe) { ge_s[tid] = gain_e[tid]; be_s[tid] = bias_e[tid]; bd_s[tid] = b_edge[tid]; }
    __syncthreads();

    for (int tile = blockIdx.x; tile < Ee / 32; tile += gridDim.x) {
        const int e0 = tile * 32;
        if (tid < 32) {
            src_s[tid] = edges[e0 + tid];
            dst_s[tid] = edges[Ee + e0 + tid];
        }
        {
            const float4* asrc = (const float4*)(ain + (size_t)e0 * EFe);
            float4* adst = (float4*)a_s;
            for (int i = tid; i < 32 * EFe / 4; i += 256) adst[i] = asrc[i];
        }
        __syncthreads();

        // LN over 64 edge features, apply g_edge / be_edge
        #pragma unroll
        for (int q = 0; q < 4; q++) {
            int r = warp * 4 + q;
            float x0 = a_s[r * EFe + lane];
            float x1 = a_s[r * EFe + lane + 32];
            float s = x0 + x1;
            float ss = fmaf(x0, x0, x1 * x1);
            #pragma unroll
            for (int o = 16; o > 0; o >>= 1) {
                s  += __shfl_xor_sync(0xffffffffu, s, o);
                ss += __shfl_xor_sync(0xffffffffu, ss, o);
            }
            float mu = s * (1.f / EFe);
            float rstd = rsqrtf(ss * (1.f / EFe) - mu * mu + 1e-5f);
            an_s[r * EFe + lane]      = (x0 - mu) * rstd * ge_s[lane]      + be_s[lane];
            an_s[r * EFe + lane + 32] = (x1 - mu) * rstd * ge_s[lane + 32] + be_s[lane + 32];
        }
        __syncthreads();

        // GEMM1: m = silu(an @ w_a + hsrc[src] + hdst[dst])
        {
            float acc[4][4];
            #pragma unroll
            for (int i = 0; i < 4; i++) { acc[i][0]=0.f; acc[i][1]=0.f; acc[i][2]=0.f; acc[i][3]=0.f; }
            #pragma unroll 4
            for (int k = 0; k < EFe; k++) {
                float4 w4 = ((const float4*)(wa_s + k * Ff))[lane];
                #pragma unroll
                for (int i = 0; i < 4; i++) {
                    float av = an_s[(warp * 4 + i) * EFe + k];
                    acc[i][0] = fmaf(av, w4.x, acc[i][0]);
                    acc[i][1] = fmaf(av, w4.y, acc[i][1]);
                    acc[i][2] = fmaf(av, w4.z, acc[i][2]);
                    acc[i][3] = fmaf(av, w4.w, acc[i][3]);
                }
            }
            #pragma unroll
            for (int i = 0; i < 4; i++) {
                int r = warp * 4 + i;
                int s = src_s[r], d = dst_s[r];
                float4 hs = ((const float4*)(g_hsrc + (size_t)s * Ff))[lane];
                float4 hd = ((const float4*)(g_hdst + (size_t)d * Ff))[lane];
                float4 m4;
                m4.x = siluf(acc[i][0] + hs.x + hd.x);
                m4.y = siluf(acc[i][1] + hs.y + hd.y);
                m4.z = siluf(acc[i][2] + hs.z + hd.z);
                m4.w = siluf(acc[i][3] + hs.w + hd.w);
                ((float4*)(m_s + r * 136))[lane] = m4;
            }
        }
        __syncthreads();

        // GEMM2 (fused): [32 x 200] = m @ [w_vatt | w_edge]
        {
            float acc[4][7];
            #pragma unroll
            for (int i = 0; i < 4; i++)
                #pragma unroll
                for (int j = 0; j < 7; j++) acc[i][j] = 0.f;
            #pragma unroll 4
            for (int k = 0; k < Ff; k++) {
                float mv[4];
                #pragma unroll
                for (int i = 0; i < 4; i++) mv[i] = m_s[(warp * 4 + i) * 136 + k];
                #pragma unroll
                for (int j = 0; j < 7; j++) {
                    float wv = wc_s[k * 224 + lane + 32 * j];
                    #pragma unroll
                    for (int i = 0; i < 4; i++) acc[i][j] = fmaf(mv[i], wv, acc[i][j]);
                }
            }
            #pragma unroll
            for (int j = 0; j < 7; j++) {
                int c = lane + 32 * j;
                if (c < Ff) {
                    #pragma unroll
                    for (int i = 0; i < 4; i++) {
                        int e = e0 + warp * 4 + i;
                        g_v[(size_t)e * Ff + c] = acc[i][j];
                    }
                } else if (c < 136) {
                    int h = c - Ff;
                    #pragma unroll
                    for (int i = 0; i < 4; i++) {
                        int r = warp * 4 + i;
                        int e = e0 + r;
                        float wv = acc[i][j];
                        g_w[(size_t)e * Hh + h] = wv;
                        atomicMaxF(&g_wmax[src_s[r] * Hh + h], wv);
                    }
                } else if (c < 200) {
                    int k2 = c - 136;
                    #pragma unroll
                    for (int i = 0; i < 4; i++) {
                        int r = warp * 4 + i;
                        int e = e0 + r;
                        aout[(size_t)e * EFe + k2] = a_s[r * EFe + k2] + acc[i][j] + bd_s[k2];
                    }
                }
            }
        }
        __syncthreads();
    }
}

// ---------------- segment softmax pass 1: exp(w - max), accumulate sums -----------
__global__ void k_seg1(const int* __restrict__ edges) {
    int idx = blockIdx.x * 256 + threadIdx.x;
    if (idx >= Ee * Hh) return;
    int e = idx >> 3, h = idx & 7;
    int s = edges[e];
    float we = __expf(g_w[idx] - g_wmax[s * Hh + h]);
    g_w[idx] = we;
    atomicAdd(&g_wsum[s * Hh + h], we);
}

// ---------------- segment softmax pass 2: o += wsm * v (one warp per edge) --------
__global__ void k_seg2(const int* __restrict__ edges) {
    int gwarp = (blockIdx.x * 256 + threadIdx.x) >> 5;
    int lane = threadIdx.x & 31;
    if (gwarp >= Ee) return;
    int e = gwarp;
    int s = edges[e];
    int h = lane >> 2;                      // col = lane*4 .. lane*4+3, head = col/16
    float wsm = g_w[(size_t)e * Hh + h] / (g_wsum[s * Hh + h] + 1e-16f);
    float4 v4 = ((const float4*)(g_v + (size_t)e * Ff))[lane];
    float* ob = g_o + (size_t)s * Ff + lane * 4;
    atomicAdd(ob + 0, wsm * v4.x);
    atomicAdd(ob + 1, wsm * v4.y);
    atomicAdd(ob + 2, wsm * v4.z);
    atomicAdd(ob + 3, wsm * v4.w);
}

// ---------------- node kernel 2: h_mid = input + o @ w_out + b_out; ada_ln(mlp) ---
__global__ __launch_bounds__(256) void k_node2(const float* __restrict__ input,
                                               const int* __restrict__ batch,
                                               const float* __restrict__ w_out,
                                               const float* __restrict__ b_out) {
    extern __shared__ float sm[];
    float* w_s  = sm;                 // 128*128
    float* o_s  = sm + Ff * Ff;       // 32*136
    float* hm_s = o_s + 32 * 136;     // 32*136
    const int tid = threadIdx.x;
    const int warp = tid >> 5, lane = tid & 31;
    const int nb = blockIdx.x * 32;
    {
        const float4* ws = (const float4*)w_out;
        float4* wd = (float4*)w_s;
        for (int i = tid; i < Ff * Ff / 4; i += 256) wd[i] = ws[i];
    }
    for (int i = tid; i < 32 * Ff / 4; i += 256) {
        int r = i >> 5, c4 = i & 31;
        ((float4*)(o_s + r * 136))[c4] = ((const float4*)(g_o + (size_t)(nb + r) * Ff))[c4];
    }
    __syncthreads();

    float acc[4][4];
    #pragma unroll
    for (int i = 0; i < 4; i++) { acc[i][0]=0.f; acc[i][1]=0.f; acc[i][2]=0.f; acc[i][3]=0.f; }
    #pragma unroll 4
    for (int k = 0; k < Ff; k++) {
        float4 w4 = ((const float4*)(w_s + k * Ff))[lane];
        #pragma unroll
        for (int i = 0; i < 4; i++) {
            float ov = o_s[(warp * 4 + i) * 136 + k];
            acc[i][0] = fmaf(ov, w4.x, acc[i][0]);
            acc[i][1] = fmaf(ov, w4.y, acc[i][1]);
            acc[i][2] = fmaf(ov, w4.z, acc[i][2]);
            acc[i][3] = fmaf(ov, w4.w, acc[i][3]);
        }
    }
    float4 b4 = ((const float4*)b_out)[lane];
    #pragma unroll
    for (int i = 0; i < 4; i++) {
        int r = warp * 4 + i;
        int n = nb + r;
        float4 in4 = ((const float4*)(input + (size_t)n * Ff))[lane];
        float4 h4;
        h4.x = acc[i][0] + in4.x + b4.x;
        h4.y = acc[i][1] + in4.y + b4.y;
        h4.z = acc[i][2] + in4.z + b4.z;
        h4.w = acc[i][3] + in4.w + b4.w;
        ((float4*)(hm_s + r * 136))[lane] = h4;
        ((float4*)(g_hmid + (size_t)n * Ff))[lane] = h4;
    }
    __syncthreads();

    #pragma unroll
    for (int q = 0; q < 4; q++) {
        int r = warp * 4 + q;
        int n = nb + r;
        float4 x = ((const float4*)(hm_s + r * 136))[lane];
        float s  = x.x + x.y + x.z + x.w;
        float ss = fmaf(x.x, x.x, fmaf(x.y, x.y, fmaf(x.z, x.z, x.w * x.w)));
        #pragma unroll
        for (int o = 16; o > 0; o >>= 1) {
            s  += __shfl_xor_sync(0xffffffffu, s, o);
            ss += __shfl_xor_sync(0xffffffffu, ss, o);
        }
        float mu = s * (1.f / Ff);
        float rstd = rsqrtf(ss * (1.f / Ff) - mu * mu + 1e-5f);
        int bix = batch[n];
        const float* sb = g_sb_mlp + bix * F2;
        float4 sc = *((const float4*)(sb + lane * 4));
        float4 sh = *((const float4*)(sb + Ff + lane * 4));
        float4 o4;
        o4.x = (x.x - mu) * rstd * (1.f + sc.x) + sh.x;
        o4.y = (x.y - mu) * rstd * (1.f + sc.y) + sh.y;
        o4.z = (x.z - mu) * rstd * (1.f + sc.z) + sh.z;
        o4.w = (x.w - mu) * rstd * (1.f + sc.w) + sh.w;
        ((float4*)(g_xn + (size_t)n * Ff))[lane] = o4;
    }
}

// ---------------- MLP kernel: out = h_mid + silu(xn @ w1 + b1) @ w2 + b2 ----------
__global__ __launch_bounds__(256) void k_mlp(const float* __restrict__ w1,
                                             const float* __restrict__ b1,
                                             const float* __restrict__ w2,
                                             const float* __restrict__ b2,
                                             float* __restrict__ hout) {
    extern __shared__ float sm[];
    float* xn_s = sm;                 // 32*136
    float* w_s  = sm + 32 * 136;      // 128*128 (reused for w1 / w2 chunks)
    float* t_s  = w_s + Ff * Ff;      // 32*136
    const int tid = threadIdx.x;
    const int warp = tid >> 5, lane = tid & 31;
    const int nb = blockIdx.x * 32;

    for (int i = tid; i < 32 * Ff / 4; i += 256) {
        int r = i >> 5, c4 = i & 31;
        ((float4*)(xn_s + r * 136))[c4] = ((const float4*)(g_xn + (size_t)(nb + r) * Ff))[c4];
    }
    float oacc[4][4];
    #pragma unroll
    for (int i = 0; i < 4; i++) { oacc[i][0]=0.f; oacc[i][1]=0.f; oacc[i][2]=0.f; oacc[i][3]=0.f; }

    for (int ch = 0; ch < 4; ch++) {
        __syncthreads();
        for (int i = tid; i < Ff * Ff; i += 256) {
            int k = i >> 7, c = i & 127;
            w_s[i] = w1[k * 512 + ch * 128 + c];
        }
        __syncthreads();
        float acc[4][4];
        #pragma unroll
        for (int i = 0; i < 4; i++) { acc[i][0]=0.f; acc[i][1]=0.f; acc[i][2]=0.f; acc[i][3]=0.f; }
        #pragma unroll 4
        for (int k = 0; k < Ff; k++) {
            float4 w4 = ((const float4*)(w_s + k * Ff))[lane];
            #pragma unroll
            for (int i = 0; i < 4; i++) {
                float xv = xn_s[(warp * 4 + i) * 136 + k];
                acc[i][0] = fmaf(xv, w4.x, acc[i][0]);
                acc[i][1] = fmaf(xv, w4.y, acc[i][1]);
                acc[i][2] = fmaf(xv, w4.z, acc[i][2]);
                acc[i][3] = fmaf(xv, w4.w, acc[i][3]);
            }
        }
        float4 b14 = ((const float4*)b1)[ch * 32 + lane];
        #pragma unroll
        for (int i = 0; i < 4; i++) {
            int r = warp * 4 + i;
            float4 t4;
            t4.x = siluf(acc[i][0] + b14.x);
            t4.y = siluf(acc[i][1] + b14.y);
            t4.z = siluf(acc[i][2] + b14.z);
            t4.w = siluf(acc[i][3] + b14.w);
            ((float4*)(t_s + r * 136))[lane] = t4;
        }
        __syncthreads();
        {
            const float4* ws = (const float4*)(w2 + (size_t)ch * Ff * Ff);
            float4* wd = (float4*)w_s;
            for (int i = tid; i < Ff * Ff / 4; i += 256) wd[i] = ws[i];
        }
        __syncthreads();
        #pragma unroll 4
        for (int k = 0; k < Ff; k++) {
            float4 w4 = ((const float4*)(w_s + k * Ff))[lane];
            #pragma unroll
            for (int i = 0; i < 4; i++) {
                float tv = t_s[(warp * 4 + i) * 136 + k];
                oacc[i][0] = fmaf(tv, w4.x, oacc[i][0]);
                oacc[i][1] = fmaf(tv, w4.y, oacc[i][1]);
                oacc[i][2] = fmaf(tv, w4.z, oacc[i][2]);
                oacc[i][3] = fmaf(tv, w4.w, oacc[i][3]);
            }
        }
    }
    float4 b24 = ((const float4*)b2)[lane];
    #pragma unroll
    for (int i = 0; i < 4; i++) {
        int n = nb + warp * 4 + i;
        float4 hm = ((const float4*)(g_hmid + (size_t)n * Ff))[lane];
        float4 r4;
        r4.x = oacc[i][0] + hm.x + b24.x;
        r4.y = oacc[i][1] + hm.y + b24.y;
        r4.z = oacc[i][2] + hm.z + b24.z;
        r4.w = oacc[i][3] + hm.w + b24.w;
        ((float4*)(hout + (size_t)n * Ff))[lane] = r4;
    }
}

// ---------------- launcher ---------------------------------------------------------
extern "C" void kernel_launch(void* const* d_in, const int* in_sizes, int n_in,
                              void* d_out, int out_size) {
    const float* input     = (const float*)d_in[0];
    const float* cond      = (const float*)d_in[1];
    const float* a         = (const float*)d_in[2];
    const int*   batch     = (const int*)d_in[3];
    const int*   edges     = (const int*)d_in[4];
    const float* w_ada_mix = (const float*)d_in[5];
    const float* b_ada_mix = (const float*)d_in[6];
    const float* w_h       = (const float*)d_in[7];
    const float* b_h       = (const float*)d_in[8];
    const float* w_a       = (const float*)d_in[9];
    const float* w_vatt    = (const float*)d_in[10];
    const float* w_out     = (const float*)d_in[11];
    const float* b_out     = (const float*)d_in[12];
    const float* g_edge_p  = (const float*)d_in[13];
    const float* be_edge_p = (const float*)d_in[14];
    const float* w_edge    = (const float*)d_in[15];
    const float* b_edge    = (const float*)d_in[16];
    const float* w_ada_mlp = (const float*)d_in[17];
    const float* b_ada_mlp = (const float*)d_in[18];
    const float* w1        = (const float*)d_in[19];
    const float* b1        = (const float*)d_in[20];
    const float* w2        = (const float*)d_in[21];
    const float* b2        = (const float*)d_in[22];

    float* hout = (float*)d_out;                       // h: [N, F]
    float* aout = (float*)d_out + (size_t)Nn * Ff;     // a_out: [E, EF]

    const int SM_NODE1 = (Ff * F2 + 32 * 136) * 4;                                  // 148480
    const int SM_EDGE  = (EFe * Ff + Ff * 224 + 2 * 32 * EFe + 32 * 136 + 3 * EFe) * 4 + 64 * 4; // 182272
    const int SM_NODE2 = (Ff * Ff + 2 * 32 * 136) * 4;                              // 100352
    const int SM_MLP   = (Ff * Ff + 2 * 32 * 136) * 4;                              // 100352

    cudaFuncSetAttribute(k_node1, cudaFuncAttributeMaxDynamicSharedMemorySize, SM_NODE1);
    cudaFuncSetAttribute(k_edge,  cudaFuncAttributeMaxDynamicSharedMemorySize, SM_EDGE);
    cudaFuncSetAttribute(k_node2, cudaFuncAttributeMaxDynamicSharedMemorySize, SM_NODE2);
    cudaFuncSetAttribute(k_mlp,   cudaFuncAttributeMaxDynamicSharedMemorySize, SM_MLP);

    k_init<<<(Nn * Ff + 255) / 256, 256>>>();
    k_cond<<<dim3(Gg, 2), 256>>>(cond, w_ada_mix, b_ada_mix, w_ada_mlp, b_ada_mlp);
    k_node1<<<Nn / 32, 256, SM_NODE1>>>(input, batch, w_h, b_h);
    k_edge<<<1480, 256, SM_EDGE>>>(a, edges, w_a, w_vatt, w_edge,
                                   g_edge_p, be_edge_p, b_edge, aout);
    k_seg1<<<(Ee * Hh + 255) / 256, 256>>>(edges);
    k_seg2<<<(Ee * 32 + 255) / 256, 256>>>(edges);
    k_node2<<<Nn / 32, 256, SM_NODE2>>>(input, batch, w_out, b_out);
    k_mlp<<<Nn / 32, 256, SM_MLP>>>(w1, b1, w2, b2, hout);
}

// round 2
// speedup vs baseline: 1.3753x; 1.3753x over previous
#include <cuda_runtime.h>
#include <cstdint>
#include <cstddef>

#define Nn 20000
#define Ee 320000
#define Ff 128
#define Hh 8
#define EFe 64
#define Aa 128
#define Gg 32
#define F2 256
#define TILE_E 64
#define TILE_N 64

// ---------------- scratch (device globals; no allocations allowed) ----------------
__device__ float g_sb_mix[Gg * F2];
__device__ float g_sb_mlp[Gg * F2];
__device__ float g_hsrc[(size_t)Nn * Ff];
__device__ float g_hdst[(size_t)Nn * Ff];
__device__ float g_v[(size_t)Ee * Ff];      // per-edge values (164 MB)
__device__ float g_w[(size_t)Ee * Hh];      // per-edge logits, then exp(w - max)
__device__ float g_wmax[Nn * Hh];
__device__ float g_wsum[Nn * Hh];
__device__ float g_o[(size_t)Nn * Ff];
__device__ float g_hmid[(size_t)Nn * Ff];
__device__ float g_xn[(size_t)Nn * Ff];

__device__ __forceinline__ float siluf(float x) { return x / (1.f + __expf(-x)); }

__device__ __forceinline__ void atomicMaxF(float* addr, float v) {
    if (v >= 0.f) atomicMax((int*)addr, __float_as_int(v));
    else          atomicMin((unsigned int*)addr, __float_as_uint(v));
}

// ---------------- init: zero accumulators, -inf maxes -----------------------------
__global__ void k_init() {
    int i = blockIdx.x * 256 + threadIdx.x;
    if (i < Nn * Ff) g_o[i] = 0.f;
    if (i < Nn * Hh) { g_wmax[i] = __int_as_float(0xff800000); g_wsum[i] = 0.f; }
}

// ---------------- cond GEMMs: sb = cond @ w + b for mix and mlp -------------------
__global__ __launch_bounds__(256) void k_cond(const float* __restrict__ cond,
                                              const float* __restrict__ w_mix,
                                              const float* __restrict__ b_mix,
                                              const float* __restrict__ w_mlp,
                                              const float* __restrict__ b_mlp) {
    __shared__ float cs[Aa];
    int g = blockIdx.x;
    int which = blockIdx.y;
    const float* w = which ? w_mlp : w_mix;
    const float* b = which ? b_mlp : b_mix;
    float* outp = which ? g_sb_mlp : g_sb_mix;
    int t = threadIdx.x;
    if (t < Aa) cs[t] = cond[g * Aa + t];
    __syncthreads();
    float acc = b[t];
    #pragma unroll 8
    for (int k = 0; k < Aa; k++) acc = fmaf(cs[k], w[k * F2 + t], acc);
    outp[g * F2 + t] = acc;
}

// ---------------- node kernel 1: ada_ln(mix) + hh = x @ w_h + b_h -----------------
__global__ __launch_bounds__(512) void k_node1(const float* __restrict__ input,
                                               const int* __restrict__ batch,
                                               const float* __restrict__ w_h,
                                               const float* __restrict__ b_h) {
    extern __shared__ float sm[];
    float* w_s  = sm;              // 128*256
    float* xm_s = sm + Ff * F2;    // 64*136 (padded)
    const int tid = threadIdx.x;
    const int warp = tid >> 5, lane = tid & 31;
    const int nb = blockIdx.x * TILE_N;

    {
        const float4* ws = (const float4*)w_h;
        float4* wd = (float4*)w_s;
        for (int i = tid; i < Ff * F2 / 4; i += 512) wd[i] = ws[i];
    }
    #pragma unroll
    for (int q = 0; q < 4; q++) {
        int r = warp * 4 + q;
        int n = nb + r;
        int nc = n < Nn ? n : Nn - 1;
        float4 x = ((const float4*)(input + (size_t)nc * Ff))[lane];
        float s  = x.x + x.y + x.z + x.w;
        float ss = fmaf(x.x, x.x, fmaf(x.y, x.y, fmaf(x.z, x.z, x.w * x.w)));
        #pragma unroll
        for (int o = 16; o > 0; o >>= 1) {
            s  += __shfl_xor_sync(0xffffffffu, s, o);
            ss += __shfl_xor_sync(0xffffffffu, ss, o);
        }
        float mu = s * (1.f / Ff);
        float rstd = rsqrtf(ss * (1.f / Ff) - mu * mu + 1e-5f);
        int bix = batch[nc];
        const float* sb = g_sb_mix + bix * F2;
        float4 sc = *((const float4*)(sb + lane * 4));
        float4 sh = *((const float4*)(sb + Ff + lane * 4));
        float4 o4;
        o4.x = (x.x - mu) * rstd * (1.f + sc.x) + sh.x;
        o4.y = (x.y - mu) * rstd * (1.f + sc.y) + sh.y;
        o4.z = (x.z - mu) * rstd * (1.f + sc.z) + sh.z;
        o4.w = (x.w - mu) * rstd * (1.f + sc.w) + sh.w;
        ((float4*)(xm_s + r * 136))[lane] = o4;
    }
    __syncthreads();

    float acc[4][8];
    #pragma unroll
    for (int i = 0; i < 4; i++)
        #pragma unroll
        for (int j = 0; j < 8; j++) acc[i][j] = 0.f;

    #pragma unroll 4
    for (int k = 0; k < Ff; k++) {
        float xa[4];
        #pragma unroll
        for (int i = 0; i < 4; i++) xa[i] = xm_s[(warp * 4 + i) * 136 + k];
        #pragma unroll
        for (int j = 0; j < 8; j++) {
            float wv = w_s[k * F2 + lane + 32 * j];
            #pragma unroll
            for (int i = 0; i < 4; i++) acc[i][j] = fmaf(xa[i], wv, acc[i][j]);
        }
    }
    #pragma unroll
    for (int j = 0; j < 8; j++) {
        int c = lane + 32 * j;
        float bb = __ldg(b_h + c);
        #pragma unroll
        for (int i = 0; i < 4; i++) {
            int n = nb + warp * 4 + i;
            if (n < Nn) {
                float v = acc[i][j] + bb;
                if (c < Ff) g_hsrc[(size_t)n * Ff + c] = v;
                else        g_hdst[(size_t)n * Ff + (c - Ff)] = v;
            }
        }
    }
}

// ---------------- edge kernel: LN(a), GEMM 64->128 + gathers + silu, GEMM 128->200 -
__global__ __launch_bounds__(512) void k_edge(const float* __restrict__ ain,
                                              const int* __restrict__ edges,
                                              const float* __restrict__ w_a,
                                              const float* __restrict__ w_vatt,
                                              const float* __restrict__ w_edge,
                                              const float* __restrict__ gain_e,
                                              const float* __restrict__ bias_e,
                                              const float* __restrict__ b_edge,
                                              float* __restrict__ aout) {
    extern __shared__ float sm[];
    float* wa_s = sm;                         // 64*128
    float* wc_s = wa_s + EFe * Ff;            // 128*224
    float* a_s  = wc_s + Ff * 224;            // 64*64
    float* an_s = a_s + TILE_E * EFe;         // 64*64
    float* m_s  = an_s + TILE_E * EFe;        // 64*136
    float* ge_s = m_s + TILE_E * 136;         // 64
    float* be_s = ge_s + EFe;                 // 64
    float* bd_s = be_s + EFe;                 // 64
    int*   src_s = (int*)(bd_s + EFe);        // 64
    int*   dst_s = src_s + TILE_E;            // 64
    const int tid = threadIdx.x;
    const int warp = tid >> 5, lane = tid & 31;

    for (int i = tid; i < EFe * Ff; i += 512) wa_s[i] = w_a[i];
    for (int i = tid; i < Ff * 224; i += 512) {
        int k = i / 224, c = i - k * 224;
        float v = 0.f;
        if (c < 136)      v = w_vatt[k * 136 + c];
        else if (c < 200) v = w_edge[k * EFe + (c - 136)];
        wc_s[i] = v;
    }
    if (tid < EFe) { ge_s[tid] = gain_e[tid]; be_s[tid] = bias_e[tid]; bd_s[tid] = b_edge[tid]; }
    __syncthreads();

    for (int tile = blockIdx.x; tile < Ee / TILE_E; tile += gridDim.x) {
        const int e0 = tile * TILE_E;
        if (tid < TILE_E) {
            src_s[tid] = edges[e0 + tid];
            dst_s[tid] = edges[Ee + e0 + tid];
        }
        {
            const float4* asrc = (const float4*)(ain + (size_t)e0 * EFe);
            float4* adst = (float4*)a_s;
            for (int i = tid; i < TILE_E * EFe / 4; i += 512) adst[i] = asrc[i];
        }
        __syncthreads();

        // LN over 64 edge features, apply g_edge / be_edge
        #pragma unroll
        for (int q = 0; q < 4; q++) {
            int r = warp * 4 + q;
            float x0 = a_s[r * EFe + lane];
            float x1 = a_s[r * EFe + lane + 32];
            float s = x0 + x1;
            float ss = fmaf(x0, x0, x1 * x1);
            #pragma unroll
            for (int o = 16; o > 0; o >>= 1) {
                s  += __shfl_xor_sync(0xffffffffu, s, o);
                ss += __shfl_xor_sync(0xffffffffu, ss, o);
            }
            float mu = s * (1.f / EFe);
            float rstd = rsqrtf(ss * (1.f / EFe) - mu * mu + 1e-5f);
            an_s[r * EFe + lane]      = (x0 - mu) * rstd * ge_s[lane]      + be_s[lane];
            an_s[r * EFe + lane + 32] = (x1 - mu) * rstd * ge_s[lane + 32] + be_s[lane + 32];
        }
        __syncthreads();

        // GEMM1: m = silu(an @ w_a + hsrc[src] + hdst[dst])
        {
            float acc[4][4];
            #pragma unroll
            for (int i = 0; i < 4; i++) { acc[i][0]=0.f; acc[i][1]=0.f; acc[i][2]=0.f; acc[i][3]=0.f; }
            #pragma unroll 4
            for (int k = 0; k < EFe; k++) {
                float4 w4 = ((const float4*)(wa_s + k * Ff))[lane];
                #pragma unroll
                for (int i = 0; i < 4; i++) {
                    float av = an_s[(warp * 4 + i) * EFe + k];
                    acc[i][0] = fmaf(av, w4.x, acc[i][0]);
                    acc[i][1] = fmaf(av, w4.y, acc[i][1]);
                    acc[i][2] = fmaf(av, w4.z, acc[i][2]);
                    acc[i][3] = fmaf(av, w4.w, acc[i][3]);
                }
            }
            #pragma unroll
            for (int i = 0; i < 4; i++) {
                int r = warp * 4 + i;
                int s = src_s[r], d = dst_s[r];
                float4 hs = ((const float4*)(g_hsrc + (size_t)s * Ff))[lane];
                float4 hd = ((const float4*)(g_hdst + (size_t)d * Ff))[lane];
                float4 m4;
                m4.x = siluf(acc[i][0] + hs.x + hd.x);
                m4.y = siluf(acc[i][1] + hs.y + hd.y);
                m4.z = siluf(acc[i][2] + hs.z + hd.z);
                m4.w = siluf(acc[i][3] + hs.w + hd.w);
                ((float4*)(m_s + r * 136))[lane] = m4;
            }
        }
        __syncthreads();

        // GEMM2 (fused): [64 x 200] = m @ [w_vatt | w_edge]
        {
            float acc[4][7];
            #pragma unroll
            for (int i = 0; i < 4; i++)
                #pragma unroll
                for (int j = 0; j < 7; j++) acc[i][j] = 0.f;
            #pragma unroll 4
            for (int k = 0; k < Ff; k++) {
                float mv[4];
                #pragma unroll
                for (int i = 0; i < 4; i++) mv[i] = m_s[(warp * 4 + i) * 136 + k];
                #pragma unroll
                for (int j = 0; j < 7; j++) {
                    float wv = wc_s[k * 224 + lane + 32 * j];
                    #pragma unroll
                    for (int i = 0; i < 4; i++) acc[i][j] = fmaf(mv[i], wv, acc[i][j]);
                }
            }
            #pragma unroll
            for (int j = 0; j < 7; j++) {
                int c = lane + 32 * j;
                if (c < Ff) {
                    #pragma unroll
                    for (int i = 0; i < 4; i++) {
                        int e = e0 + warp * 4 + i;
                        g_v[(size_t)e * Ff + c] = acc[i][j];
                    }
                } else if (c < 136) {
                    int h = c - Ff;
                    #pragma unroll
                    for (int i = 0; i < 4; i++) {
                        int r = warp * 4 + i;
                        int e = e0 + r;
                        float wv = acc[i][j];
                        g_w[(size_t)e * Hh + h] = wv;
                        atomicMaxF(&g_wmax[src_s[r] * Hh + h], wv);
                    }
                } else if (c < 200) {
                    int k2 = c - 136;
                    #pragma unroll
                    for (int i = 0; i < 4; i++) {
                        int r = warp * 4 + i;
                        int e = e0 + r;
                        aout[(size_t)e * EFe + k2] = a_s[r * EFe + k2] + acc[i][j] + bd_s[k2];
                    }
                }
            }
        }
        __syncthreads();
    }
}

// ---------------- segment softmax pass 1: exp(w - max), accumulate sums -----------
__global__ void k_seg1(const int* __restrict__ edges) {
    int idx = blockIdx.x * 256 + threadIdx.x;
    if (idx >= Ee * Hh) return;
    int e = idx >> 3, h = idx & 7;
    int s = edges[e];
    float we = __expf(g_w[idx] - g_wmax[s * Hh + h]);
    g_w[idx] = we;
    atomicAdd(&g_wsum[s * Hh + h], we);
}

// ---------------- segment softmax pass 2: o += wsm * v (one warp per edge) --------
__global__ void k_seg2(const int* __restrict__ edges) {
    int gwarp = (blockIdx.x * 256 + threadIdx.x) >> 5;
    int lane = threadIdx.x & 31;
    if (gwarp >= Ee) return;
    int e = gwarp;
    int s = edges[e];
    int h = lane >> 2;
    float wsm = g_w[(size_t)e * Hh + h] / (g_wsum[s * Hh + h] + 1e-16f);
    float4 v4 = ((const float4*)(g_v + (size_t)e * Ff))[lane];
    float* ob = g_o + (size_t)s * Ff + lane * 4;
    asm volatile("red.global.add.v4.f32 [%0], {%1, %2, %3, %4};"
                 :: "l"(ob), "f"(wsm * v4.x), "f"(wsm * v4.y),
                    "f"(wsm * v4.z), "f"(wsm * v4.w) : "memory");
}

// ---------------- node kernel 2: h_mid = input + o @ w_out + b_out; ada_ln(mlp) ---
__global__ __launch_bounds__(512) void k_node2(const float* __restrict__ input,
                                               const int* __restrict__ batch,
                                               const float* __restrict__ w_out,
                                               const float* __restrict__ b_out) {
    extern __shared__ float sm[];
    float* w_s  = sm;                 // 128*128
    float* o_s  = sm + Ff * Ff;       // 64*136
    float* hm_s = o_s + TILE_N * 136; // 64*136
    const int tid = threadIdx.x;
    const int warp = tid >> 5, lane = tid & 31;
    const int nb = blockIdx.x * TILE_N;
    {
        const float4* ws = (const float4*)w_out;
        float4* wd = (float4*)w_s;
        for (int i = tid; i < Ff * Ff / 4; i += 512) wd[i] = ws[i];
    }
    for (int i = tid; i < TILE_N * Ff / 4; i += 512) {
        int r = i >> 5, c4 = i & 31;
        int n = nb + r;
        int nc = n < Nn ? n : Nn - 1;
        ((float4*)(o_s + r * 136))[c4] = ((const float4*)(g_o + (size_t)nc * Ff))[c4];
    }
    __syncthreads();

    float acc[4][4];
    #pragma unroll
    for (int i = 0; i < 4; i++) { acc[i][0]=0.f; acc[i][1]=0.f; acc[i][2]=0.f; acc[i][3]=0.f; }
    #pragma unroll 4
    for (int k = 0; k < Ff; k++) {
        float4 w4 = ((const float4*)(w_s + k * Ff))[lane];
        #pragma unroll
        for (int i = 0; i < 4; i++) {
            float ov = o_s[(warp * 4 + i) * 136 + k];
            acc[i][0] = fmaf(ov, w4.x, acc[i][0]);
            acc[i][1] = fmaf(ov, w4.y, acc[i][1]);
            acc[i][2] = fmaf(ov, w4.z, acc[i][2]);
            acc[i][3] = fmaf(ov, w4.w, acc[i][3]);
        }
    }
    float4 b4 = ((const float4*)b_out)[lane];
    #pragma unroll
    for (int i = 0; i < 4; i++) {
        int r = warp * 4 + i;
        int n = nb + r;
        int nc = n < Nn ? n : Nn - 1;
        float4 in4 = ((const float4*)(input + (size_t)nc * Ff))[lane];
        float4 h4;
        h4.x = acc[i][0] + in4.x + b4.x;
        h4.y = acc[i][1] + in4.y + b4.y;
        h4.z = acc[i][2] + in4.z + b4.z;
        h4.w = acc[i][3] + in4.w + b4.w;
        ((float4*)(hm_s + r * 136))[lane] = h4;
        if (n < Nn) ((float4*)(g_hmid + (size_t)n * Ff))[lane] = h4;
    }
    __syncthreads();

    #pragma unroll
    for (int q = 0; q < 4; q++) {
        int r = warp * 4 + q;
        int n = nb + r;
        if (n >= Nn) continue;
        float4 x = ((const float4*)(hm_s + r * 136))[lane];
        float s  = x.x + x.y + x.z + x.w;
        float ss = fmaf(x.x, x.x, fmaf(x.y, x.y, fmaf(x.z, x.z, x.w * x.w)));
        #pragma unroll
        for (int o = 16; o > 0; o >>= 1) {
            s  += __shfl_xor_sync(0xffffffffu, s, o);
            ss += __shfl_xor_sync(0xffffffffu, ss, o);
        }
        float mu = s * (1.f / Ff);
        float rstd = rsqrtf(ss * (1.f / Ff) - mu * mu + 1e-5f);
        int bix = batch[n];
        const float* sb = g_sb_mlp + bix * F2;
        float4 sc = *((const float4*)(sb + lane * 4));
        float4 sh = *((const float4*)(sb + Ff + lane * 4));
        float4 o4;
        o4.x = (x.x - mu) * rstd * (1.f + sc.x) + sh.x;
        o4.y = (x.y - mu) * rstd * (1.f + sc.y) + sh.y;
        o4.z = (x.z - mu) * rstd * (1.f + sc.z) + sh.z;
        o4.w = (x.w - mu) * rstd * (1.f + sc.w) + sh.w;
        ((float4*)(g_xn + (size_t)n * Ff))[lane] = o4;
    }
}

// ---------------- MLP kernel: out = h_mid + silu(xn @ w1 + b1) @ w2 + b2 ----------
__global__ __launch_bounds__(512) void k_mlp(const float* __restrict__ w1,
                                             const float* __restrict__ b1,
                                             const float* __restrict__ w2,
                                             const float* __restrict__ b2,
                                             float* __restrict__ hout) {
    extern __shared__ float sm[];
    float* xn_s = sm;                   // 64*136
    float* w_s  = sm + TILE_N * 136;    // 128*128
    float* t_s  = w_s + Ff * Ff;        // 64*136
    const int tid = threadIdx.x;
    const int warp = tid >> 5, lane = tid & 31;
    const int nb = blockIdx.x * TILE_N;

    for (int i = tid; i < TILE_N * Ff / 4; i += 512) {
        int r = i >> 5, c4 = i & 31;
        int n = nb + r;
        int nc = n < Nn ? n : Nn - 1;
        ((float4*)(xn_s + r * 136))[c4] = ((const float4*)(g_xn + (size_t)nc * Ff))[c4];
    }
    float oacc[4][4];
    #pragma unroll
    for (int i = 0; i < 4; i++) { oacc[i][0]=0.f; oacc[i][1]=0.f; oacc[i][2]=0.f; oacc[i][3]=0.f; }

    for (int ch = 0; ch < 4; ch++) {
        __syncthreads();
        for (int i = tid; i < Ff * Ff; i += 512) {
            int k = i >> 7, c = i & 127;
            w_s[i] = w1[k * 512 + ch * 128 + c];
        }
        __syncthreads();
        float acc[4][4];
        #pragma unroll
        for (int i = 0; i < 4; i++) { acc[i][0]=0.f; acc[i][1]=0.f; acc[i][2]=0.f; acc[i][3]=0.f; }
        #pragma unroll 4
        for (int k = 0; k < Ff; k++) {
            float4 w4 = ((const float4*)(w_s + k * Ff))[lane];
            #pragma unroll
            for (int i = 0; i < 4; i++) {
                float xv = xn_s[(warp * 4 + i) * 136 + k];
                acc[i][0] = fmaf(xv, w4.x, acc[i][0]);
                acc[i][1] = fmaf(xv, w4.y, acc[i][1]);
                acc[i][2] = fmaf(xv, w4.z, acc[i][2]);
                acc[i][3] = fmaf(xv, w4.w, acc[i][3]);
            }
        }
        float4 b14 = ((const float4*)b1)[ch * 32 + lane];
        #pragma unroll
        for (int i = 0; i < 4; i++) {
            int r = warp * 4 + i;
            float4 t4;
            t4.x = siluf(acc[i][0] + b14.x);
            t4.y = siluf(acc[i][1] + b14.y);
            t4.z = siluf(acc[i][2] + b14.z);
            t4.w = siluf(acc[i][3] + b14.w);
            ((float4*)(t_s + r * 136))[lane] = t4;
        }
        __syncthreads();
        {
            const float4* ws = (const float4*)(w2 + (size_t)ch * Ff * Ff);
            float4* wd = (float4*)w_s;
            for (int i = tid; i < Ff * Ff / 4; i += 512) wd[i] = ws[i];
        }
        __syncthreads();
        #pragma unroll 4
        for (int k = 0; k < Ff; k++) {
            float4 w4 = ((const float4*)(w_s + k * Ff))[lane];
            #pragma unroll
            for (int i = 0; i < 4; i++) {
                float tv = t_s[(warp * 4 + i) * 136 + k];
                oacc[i][0] = fmaf(tv, w4.x, oacc[i][0]);
                oacc[i][1] = fmaf(tv, w4.y, oacc[i][1]);
                oacc[i][2] = fmaf(tv, w4.z, oacc[i][2]);
                oacc[i][3] = fmaf(tv, w4.w, oacc[i][3]);
            }
        }
    }
    float4 b24 = ((const float4*)b2)[lane];
    #pragma unroll
    for (int i = 0; i < 4; i++) {
        int n = nb + warp * 4 + i;
        if (n >= Nn) continue;
        float4 hm = ((const float4*)(g_hmid + (size_t)n * Ff))[lane];
        float4 r4;
        r4.x = oacc[i][0] + hm.x + b24.x;
        r4.y = oacc[i][1] + hm.y + b24.y;
        r4.z = oacc[i][2] + hm.z + b24.z;
        r4.w = oacc[i][3] + hm.w + b24.w;
        ((float4*)(hout + (size_t)n * Ff))[lane] = r4;
    }
}

// ---------------- launcher ---------------------------------------------------------
extern "C" void kernel_launch(void* const* d_in, const int* in_sizes, int n_in,
                              void* d_out, int out_size) {
    const float* input     = (const float*)d_in[0];
    const float* cond      = (const float*)d_in[1];
    const float* a         = (const float*)d_in[2];
    const int*   batch     = (const int*)d_in[3];
    const int*   edges     = (const int*)d_in[4];
    const float* w_ada_mix = (const float*)d_in[5];
    const float* b_ada_mix = (const float*)d_in[6];
    const float* w_h       = (const float*)d_in[7];
    const float* b_h       = (const float*)d_in[8];
    const float* w_a       = (const float*)d_in[9];
    const float* w_vatt    = (const float*)d_in[10];
    const float* w_out     = (const float*)d_in[11];
    const float* b_out     = (const float*)d_in[12];
    const float* g_edge_p  = (const float*)d_in[13];
    const float* be_edge_p = (const float*)d_in[14];
    const float* w_edge    = (const float*)d_in[15];
    const float* b_edge    = (const float*)d_in[16];
    const float* w_ada_mlp = (const float*)d_in[17];
    const float* b_ada_mlp = (const float*)d_in[18];
    const float* w1        = (const float*)d_in[19];
    const float* b1        = (const float*)d_in[20];
    const float* w2        = (const float*)d_in[21];
    const float* b2        = (const float*)d_in[22];

    float* hout = (float*)d_out;                       // h: [N, F]
    float* aout = (float*)d_out + (size_t)Nn * Ff;     // a_out: [E, EF]

    const int SM_NODE1 = (Ff * F2 + TILE_N * 136) * 4;                              // 165888
    const int SM_EDGE  = (EFe * Ff + Ff * 224 + 2 * TILE_E * EFe + TILE_E * 136 + 3 * EFe) * 4
                       + 2 * TILE_E * 4;                                            // 216320
    const int SM_NODE2 = (Ff * Ff + 2 * TILE_N * 136) * 4;                          // 135168
    const int SM_MLP   = (Ff * Ff + 2 * TILE_N * 136) * 4;                          // 135168

    cudaFuncSetAttribute(k_node1, cudaFuncAttributeMaxDynamicSharedMemorySize, SM_NODE1);
    cudaFuncSetAttribute(k_edge,  cudaFuncAttributeMaxDynamicSharedMemorySize, SM_EDGE);
    cudaFuncSetAttribute(k_node2, cudaFuncAttributeMaxDynamicSharedMemorySize, SM_NODE2);
    cudaFuncSetAttribute(k_mlp,   cudaFuncAttributeMaxDynamicSharedMemorySize, SM_MLP);

    const int NT = (Nn + TILE_N - 1) / TILE_N;  // 313

    k_init<<<(Nn * Ff + 255) / 256, 256>>>();
    k_cond<<<dim3(Gg, 2), 256>>>(cond, w_ada_mix, b_ada_mix, w_ada_mlp, b_ada_mlp);
    k_node1<<<NT, 512, SM_NODE1>>>(input, batch, w_h, b_h);
    k_edge<<<296, 512, SM_EDGE>>>(a, edges, w_a, w_vatt, w_edge,
                                  g_edge_p, be_edge_p, b_edge, aout);
    k_seg1<<<(Ee * Hh + 255) / 256, 256>>>(edges);
    k_seg2<<<(Ee * 32 + 255) / 256, 256>>>(edges);
    k_node2<<<NT, 512, SM_NODE2>>>(input, batch, w_out, b_out);
    k_mlp<<<NT, 512, SM_MLP>>>(w1, b1, w2, b2, hout);
}

// round 3
// speedup vs baseline: 1.5886x; 1.1551x over previous
#include <cuda_runtime.h>
#include <cstdint>
#include <cstddef>

#define Nn 20000
#define Ee 320000
#define Ff 128
#define Hh 8
#define EFe 64
#define Aa 128
#define Gg 32
#define F2 256
#define TILE_E 64
#define TILE_N 64

// ---------------- scratch (device globals; no allocations allowed) ----------------
__device__ float g_sb_mix[Gg * F2];
__device__ float g_sb_mlp[Gg * F2];
__device__ float g_hsrc[(size_t)Nn * Ff];
__device__ float g_hdst[(size_t)Nn * Ff];
__device__ float g_wsum[Nn * Hh];
__device__ float g_o[(size_t)Nn * Ff];

__device__ __forceinline__ float siluf(float x) { return x / (1.f + __expf(-x)); }

// ---------------- init: zero accumulators ----------------------------------------
__global__ void k_init() {
    int i = blockIdx.x * 256 + threadIdx.x;
    if (i < Nn * Ff) g_o[i] = 0.f;
    if (i < Nn * Hh) g_wsum[i] = 0.f;
}

// ---------------- cond GEMMs: sb = cond @ w + b for mix and mlp -------------------
__global__ __launch_bounds__(256) void k_cond(const float* __restrict__ cond,
                                              const float* __restrict__ w_mix,
                                              const float* __restrict__ b_mix,
                                              const float* __restrict__ w_mlp,
                                              const float* __restrict__ b_mlp) {
    __shared__ float cs[Aa];
    int g = blockIdx.x;
    int which = blockIdx.y;
    const float* w = which ? w_mlp : w_mix;
    const float* b = which ? b_mlp : b_mix;
    float* outp = which ? g_sb_mlp : g_sb_mix;
    int t = threadIdx.x;
    if (t < Aa) cs[t] = cond[g * Aa + t];
    __syncthreads();
    float acc = b[t];
    #pragma unroll 8
    for (int k = 0; k < Aa; k++) acc = fmaf(cs[k], w[k * F2 + t], acc);
    outp[g * F2 + t] = acc;
}

// ---------------- node kernel 1: ada_ln(mix) + hh = x @ w_h + b_h -----------------
__global__ __launch_bounds__(512) void k_node1(const float* __restrict__ input,
                                               const int* __restrict__ batch,
                                               const float* __restrict__ w_h,
                                               const float* __restrict__ b_h) {
    extern __shared__ float sm[];
    float* w_s  = sm;              // 128*256
    float* xm_s = sm + Ff * F2;    // 64*136 (padded)
    const int tid = threadIdx.x;
    const int warp = tid >> 5, lane = tid & 31;
    const int nb = blockIdx.x * TILE_N;

    {
        const float4* ws = (const float4*)w_h;
        float4* wd = (float4*)w_s;
        for (int i = tid; i < Ff * F2 / 4; i += 512) wd[i] = ws[i];
    }
    #pragma unroll
    for (int q = 0; q < 4; q++) {
        int r = warp * 4 + q;
        int n = nb + r;
        int nc = n < Nn ? n : Nn - 1;
        float4 x = ((const float4*)(input + (size_t)nc * Ff))[lane];
        float s  = x.x + x.y + x.z + x.w;
        float ss = fmaf(x.x, x.x, fmaf(x.y, x.y, fmaf(x.z, x.z, x.w * x.w)));
        #pragma unroll
        for (int o = 16; o > 0; o >>= 1) {
            s  += __shfl_xor_sync(0xffffffffu, s, o);
            ss += __shfl_xor_sync(0xffffffffu, ss, o);
        }
        float mu = s * (1.f / Ff);
        float rstd = rsqrtf(ss * (1.f / Ff) - mu * mu + 1e-5f);
        int bix = batch[nc];
        const float* sb = g_sb_mix + bix * F2;
        float4 sc = *((const float4*)(sb + lane * 4));
        float4 sh = *((const float4*)(sb + Ff + lane * 4));
        float4 o4;
        o4.x = (x.x - mu) * rstd * (1.f + sc.x) + sh.x;
        o4.y = (x.y - mu) * rstd * (1.f + sc.y) + sh.y;
        o4.z = (x.z - mu) * rstd * (1.f + sc.z) + sh.z;
        o4.w = (x.w - mu) * rstd * (1.f + sc.w) + sh.w;
        ((float4*)(xm_s + r * 136))[lane] = o4;
    }
    __syncthreads();

    float acc[4][8];
    #pragma unroll
    for (int i = 0; i < 4; i++)
        #pragma unroll
        for (int j = 0; j < 8; j++) acc[i][j] = 0.f;

    #pragma unroll 4
    for (int k = 0; k < Ff; k++) {
        float xa[4];
        #pragma unroll
        for (int i = 0; i < 4; i++) xa[i] = xm_s[(warp * 4 + i) * 136 + k];
        #pragma unroll
        for (int j = 0; j < 8; j++) {
            float wv = w_s[k * F2 + lane + 32 * j];
            #pragma unroll
            for (int i = 0; i < 4; i++) acc[i][j] = fmaf(xa[i], wv, acc[i][j]);
        }
    }
    #pragma unroll
    for (int j = 0; j < 8; j++) {
        int c = lane + 32 * j;
        float bb = __ldg(b_h + c);
        #pragma unroll
        for (int i = 0; i < 4; i++) {
            int n = nb + warp * 4 + i;
            if (n < Nn) {
                float v = acc[i][j] + bb;
                if (c < Ff) g_hsrc[(size_t)n * Ff + c] = v;
                else        g_hdst[(size_t)n * Ff + (c - Ff)] = v;
            }
        }
    }
}

// ---------------- edge kernel: LN(a), GEMM1+gathers+silu, GEMM2, fused softmax-acc -
__global__ __launch_bounds__(512) void k_edge(const float* __restrict__ ain,
                                              const int* __restrict__ edges,
                                              const float* __restrict__ w_a,
                                              const float* __restrict__ w_vatt,
                                              const float* __restrict__ w_edge,
                                              const float* __restrict__ gain_e,
                                              const float* __restrict__ bias_e,
                                              const float* __restrict__ b_edge,
                                              float* __restrict__ aout) {
    extern __shared__ float sm[];
    float* wa_s = sm;                         // 64*128
    float* wc_s = wa_s + EFe * Ff;            // 128*224
    float* a_s  = wc_s + Ff * 224;            // 64*64
    float* an_s = a_s + TILE_E * EFe;         // 64*64
    float* m_s  = an_s + TILE_E * EFe;        // 64*136 (m, then wexp*v)
    float* ge_s = m_s + TILE_E * 136;         // 64
    float* be_s = ge_s + EFe;                 // 64
    float* bd_s = be_s + EFe;                 // 64
    int*   src_s = (int*)(bd_s + EFe);        // 64
    const int tid = threadIdx.x;
    const int warp = tid >> 5, lane = tid & 31;

    for (int i = tid; i < EFe * Ff; i += 512) wa_s[i] = w_a[i];
    for (int i = tid; i < Ff * 224; i += 512) {
        int k = i / 224, c = i - k * 224;
        float v = 0.f;
        if (c < 136)      v = w_vatt[k * 136 + c];
        else if (c < 200) v = w_edge[k * EFe + (c - 136)];
        wc_s[i] = v;
    }
    if (tid < EFe) { ge_s[tid] = gain_e[tid]; be_s[tid] = bias_e[tid]; bd_s[tid] = b_edge[tid]; }
    __syncthreads();

    for (int tile = blockIdx.x; tile < Ee / TILE_E; tile += gridDim.x) {
        const int e0 = tile * TILE_E;

        // prefetch gathers for this warp's 4 edge rows (overlaps LN + GEMM1)
        int sv[4], dv[4];
        #pragma unroll
        for (int i = 0; i < 4; i++) {
            int r = warp * 4 + i;
            sv[i] = __ldg(edges + e0 + r);
            dv[i] = __ldg(edges + Ee + e0 + r);
        }
        float4 hs4[4], hd4[4];
        #pragma unroll
        for (int i = 0; i < 4; i++) {
            hs4[i] = ((const float4*)(g_hsrc + (size_t)sv[i] * Ff))[lane];
            hd4[i] = ((const float4*)(g_hdst + (size_t)dv[i] * Ff))[lane];
        }

        if (tid < TILE_E) src_s[tid] = edges[e0 + tid];
        {
            const float4* asrc = (const float4*)(ain + (size_t)e0 * EFe);
            float4* adst = (float4*)a_s;
            for (int i = tid; i < TILE_E * EFe / 4; i += 512) adst[i] = asrc[i];
        }
        __syncthreads();

        // LN over 64 edge features, apply g_edge / be_edge
        #pragma unroll
        for (int q = 0; q < 4; q++) {
            int r = warp * 4 + q;
            float x0 = a_s[r * EFe + lane];
            float x1 = a_s[r * EFe + lane + 32];
            float s = x0 + x1;
            float ss = fmaf(x0, x0, x1 * x1);
            #pragma unroll
            for (int o = 16; o > 0; o >>= 1) {
                s  += __shfl_xor_sync(0xffffffffu, s, o);
                ss += __shfl_xor_sync(0xffffffffu, ss, o);
            }
            float mu = s * (1.f / EFe);
            float rstd = rsqrtf(ss * (1.f / EFe) - mu * mu + 1e-5f);
            an_s[r * EFe + lane]      = (x0 - mu) * rstd * ge_s[lane]      + be_s[lane];
            an_s[r * EFe + lane + 32] = (x1 - mu) * rstd * ge_s[lane + 32] + be_s[lane + 32];
        }
        __syncthreads();

        // GEMM1: m = silu(an @ w_a + hsrc[src] + hdst[dst])
        {
            float acc[4][4];
            #pragma unroll
            for (int i = 0; i < 4; i++) { acc[i][0]=0.f; acc[i][1]=0.f; acc[i][2]=0.f; acc[i][3]=0.f; }
            #pragma unroll 4
            for (int k = 0; k < EFe; k++) {
                float4 w4 = ((const float4*)(wa_s + k * Ff))[lane];
                #pragma unroll
                for (int i = 0; i < 4; i++) {
                    float av = an_s[(warp * 4 + i) * EFe + k];
                    acc[i][0] = fmaf(av, w4.x, acc[i][0]);
                    acc[i][1] = fmaf(av, w4.y, acc[i][1]);
                    acc[i][2] = fmaf(av, w4.z, acc[i][2]);
                    acc[i][3] = fmaf(av, w4.w, acc[i][3]);
                }
            }
            #pragma unroll
            for (int i = 0; i < 4; i++) {
                int r = warp * 4 + i;
                float4 m4;
                m4.x = siluf(acc[i][0] + hs4[i].x + hd4[i].x);
                m4.y = siluf(acc[i][1] + hs4[i].y + hd4[i].y);
                m4.z = siluf(acc[i][2] + hs4[i].z + hd4[i].z);
                m4.w = siluf(acc[i][3] + hs4[i].w + hd4[i].w);
                ((float4*)(m_s + r * 136))[lane] = m4;
            }
        }
        __syncthreads();

        // GEMM2 (fused): [64 x 200] = m @ [w_vatt | w_edge]
        {
            float acc[4][7];
            #pragma unroll
            for (int i = 0; i < 4; i++)
                #pragma unroll
                for (int j = 0; j < 7; j++) acc[i][j] = 0.f;
            #pragma unroll 4
            for (int k = 0; k < Ff; k++) {
                float mv[4];
                #pragma unroll
                for (int i = 0; i < 4; i++) mv[i] = m_s[(warp * 4 + i) * 136 + k];
                #pragma unroll
                for (int j = 0; j < 7; j++) {
                    float wv = wc_s[k * 224 + lane + 32 * j];
                    #pragma unroll
                    for (int i = 0; i < 4; i++) acc[i][j] = fmaf(mv[i], wv, acc[i][j]);
                }
            }

            // ---- fused softmax-numerator epilogue ----
            // head logits live in acc[i][4], lanes 0..7 (cols 128..135)
            float wexp_reg[4];
            #pragma unroll
            for (int i = 0; i < 4; i++) wexp_reg[i] = __expf(acc[i][4]);

            if (lane < Hh) {
                #pragma unroll
                for (int i = 0; i < 4; i++) {
                    float* p = g_wsum + (size_t)sv[i] * Hh + lane;
                    asm volatile("red.global.add.f32 [%0], %1;" :: "l"(p), "f"(wexp_reg[i]) : "memory");
                }
            }

            // stage wexp*v into m_s (own rows only — safe, GEMM2 reads own rows)
            #pragma unroll
            for (int j = 0; j < 4; j++) {
                int c = lane + 32 * j;
                int h = c >> 4;
                #pragma unroll
                for (int i = 0; i < 4; i++) {
                    float we = __shfl_sync(0xffffffffu, wexp_reg[i], h);
                    m_s[(warp * 4 + i) * 136 + c] = acc[i][j] * we;
                }
            }

            // a_out epilogue (cols 136..199)
            #pragma unroll
            for (int j = 4; j < 7; j++) {
                int c = lane + 32 * j;
                if (c >= 136 && c < 200) {
                    int k2 = c - 136;
                    #pragma unroll
                    for (int i = 0; i < 4; i++) {
                        int r = warp * 4 + i;
                        aout[(size_t)(e0 + r) * EFe + k2] = a_s[r * EFe + k2] + acc[i][j] + bd_s[k2];
                    }
                }
            }
        }
        __syncthreads();

        // cooperative vector reduction of wexp*v into g_o
        for (int rr = warp; rr < TILE_E; rr += 16) {
            int s = src_s[rr];
            float4 wv = ((const float4*)(m_s + rr * 136))[lane];
            float* ob = g_o + (size_t)s * Ff + lane * 4;
            asm volatile("red.global.add.v4.f32 [%0], {%1, %2, %3, %4};"
                         :: "l"(ob), "f"(wv.x), "f"(wv.y), "f"(wv.z), "f"(wv.w) : "memory");
        }
        __syncthreads();
    }
}

// ------- fused node kernel 2 + MLP:
// hm = input + (o/wsum) @ w_out + b_out ; xn = ada_ln(hm); out = hm + silu(xn@w1+b1)@w2 + b2
__global__ __launch_bounds__(512) void k_node2mlp(const float* __restrict__ input,
                                                  const int* __restrict__ batch,
                                                  const float* __restrict__ w_out,
                                                  const float* __restrict__ b_out,
                                                  const float* __restrict__ w1,
                                                  const float* __restrict__ b1,
                                                  const float* __restrict__ w2,
                                                  const float* __restrict__ b2,
                                                  float* __restrict__ hout) {
    extern __shared__ float sm[];
    float* w_s  = sm;                   // 128*128 (w_out, then w1/w2 chunks)
    float* xn_s = sm + Ff * Ff;         // 64*136
    float* t_s  = xn_s + TILE_N * 136;  // 64*136 (o staging, then silu activations)
    const int tid = threadIdx.x;
    const int warp = tid >> 5, lane = tid & 31;
    const int nb = blockIdx.x * TILE_N;

    {
        const float4* ws = (const float4*)w_out;
        float4* wd = (float4*)w_s;
        for (int i = tid; i < Ff * Ff / 4; i += 512) wd[i] = ws[i];
    }
    // stage o / wsum into t_s
    for (int i = tid; i < TILE_N * Ff / 4; i += 512) {
        int r = i >> 5, c4 = i & 31;
        int n = nb + r;
        int nc = n < Nn ? n : Nn - 1;
        float4 o4 = ((const float4*)(g_o + (size_t)nc * Ff))[c4];
        int h = c4 >> 2;
        float inv = 1.f / (g_wsum[nc * Hh + h] + 1e-16f);
        o4.x *= inv; o4.y *= inv; o4.z *= inv; o4.w *= inv;
        ((float4*)(t_s + r * 136))[c4] = o4;
    }
    __syncthreads();

    // GEMM: hm = t_s @ w_out + input + b_out (hm stays in registers)
    float acc[4][4];
    #pragma unroll
    for (int i = 0; i < 4; i++) { acc[i][0]=0.f; acc[i][1]=0.f; acc[i][2]=0.f; acc[i][3]=0.f; }
    #pragma unroll 4
    for (int k = 0; k < Ff; k++) {
        float4 w4 = ((const float4*)(w_s + k * Ff))[lane];
        #pragma unroll
        for (int i = 0; i < 4; i++) {
            float ov = t_s[(warp * 4 + i) * 136 + k];
            acc[i][0] = fmaf(ov, w4.x, acc[i][0]);
            acc[i][1] = fmaf(ov, w4.y, acc[i][1]);
            acc[i][2] = fmaf(ov, w4.z, acc[i][2]);
            acc[i][3] = fmaf(ov, w4.w, acc[i][3]);
        }
    }
    float4 hm[4];
    {
        float4 b4 = ((const float4*)b_out)[lane];
        #pragma unroll
        for (int i = 0; i < 4; i++) {
            int n = nb + warp * 4 + i;
            int nc = n < Nn ? n : Nn - 1;
            float4 in4 = ((const float4*)(input + (size_t)nc * Ff))[lane];
            hm[i].x = acc[i][0] + in4.x + b4.x;
            hm[i].y = acc[i][1] + in4.y + b4.y;
            hm[i].z = acc[i][2] + in4.z + b4.z;
            hm[i].w = acc[i][3] + in4.w + b4.w;
        }
    }

    // ada_ln(mlp) from registers -> xn_s
    #pragma unroll
    for (int q = 0; q < 4; q++) {
        int r = warp * 4 + q;
        int n = nb + r;
        int nc = n < Nn ? n : Nn - 1;
        float4 x = hm[q];
        float s  = x.x + x.y + x.z + x.w;
        float ss = fmaf(x.x, x.x, fmaf(x.y, x.y, fmaf(x.z, x.z, x.w * x.w)));
        #pragma unroll
        for (int o = 16; o > 0; o >>= 1) {
            s  += __shfl_xor_sync(0xffffffffu, s, o);
            ss += __shfl_xor_sync(0xffffffffu, ss, o);
        }
        float mu = s * (1.f / Ff);
        float rstd = rsqrtf(ss * (1.f / Ff) - mu * mu + 1e-5f);
        int bix = batch[nc];
        const float* sb = g_sb_mlp + bix * F2;
        float4 sc = *((const float4*)(sb + lane * 4));
        float4 sh = *((const float4*)(sb + Ff + lane * 4));
        float4 o4;
        o4.x = (x.x - mu) * rstd * (1.f + sc.x) + sh.x;
        o4.y = (x.y - mu) * rstd * (1.f + sc.y) + sh.y;
        o4.z = (x.z - mu) * rstd * (1.f + sc.z) + sh.z;
        o4.w = (x.w - mu) * rstd * (1.f + sc.w) + sh.w;
        ((float4*)(xn_s + r * 136))[lane] = o4;
    }
    __syncthreads();

    // MLP: out = hm + silu(xn @ w1 + b1) @ w2 + b2, chunked over the 512 hidden dim
    float oacc[4][4];
    #pragma unroll
    for (int i = 0; i < 4; i++) { oacc[i][0]=0.f; oacc[i][1]=0.f; oacc[i][2]=0.f; oacc[i][3]=0.f; }

    for (int ch = 0; ch < 4; ch++) {
        for (int i = tid; i < Ff * Ff; i += 512) {
            int k = i >> 7, c = i & 127;
            w_s[i] = w1[k * 512 + ch * 128 + c];
        }
        __syncthreads();
        float acc2[4][4];
        #pragma unroll
        for (int i = 0; i < 4; i++) { acc2[i][0]=0.f; acc2[i][1]=0.f; acc2[i][2]=0.f; acc2[i][3]=0.f; }
        #pragma unroll 4
        for (int k = 0; k < Ff; k++) {
            float4 w4 = ((const float4*)(w_s + k * Ff))[lane];
            #pragma unroll
            for (int i = 0; i < 4; i++) {
                float xv = xn_s[(warp * 4 + i) * 136 + k];
                acc2[i][0] = fmaf(xv, w4.x, acc2[i][0]);
                acc2[i][1] = fmaf(xv, w4.y, acc2[i][1]);
                acc2[i][2] = fmaf(xv, w4.z, acc2[i][2]);
                acc2[i][3] = fmaf(xv, w4.w, acc2[i][3]);
            }
        }
        float4 b14 = ((const float4*)b1)[ch * 32 + lane];
        #pragma unroll
        for (int i = 0; i < 4; i++) {
            int r = warp * 4 + i;
            float4 t4;
            t4.x = siluf(acc2[i][0] + b14.x);
            t4.y = siluf(acc2[i][1] + b14.y);
            t4.z = siluf(acc2[i][2] + b14.z);
            t4.w = siluf(acc2[i][3] + b14.w);
            ((float4*)(t_s + r * 136))[lane] = t4;
        }
        __syncthreads();
        {
            const float4* ws = (const float4*)(w2 + (size_t)ch * Ff * Ff);
            float4* wd = (float4*)w_s;
            for (int i = tid; i < Ff * Ff / 4; i += 512) wd[i] = ws[i];
        }
        __syncthreads();
        #pragma unroll 4
        for (int k = 0; k < Ff; k++) {
            float4 w4 = ((const float4*)(w_s + k * Ff))[lane];
            #pragma unroll
            for (int i = 0; i < 4; i++) {
                float tv = t_s[(warp * 4 + i) * 136 + k];
                oacc[i][0] = fmaf(tv, w4.x, oacc[i][0]);
                oacc[i][1] = fmaf(tv, w4.y, oacc[i][1]);
                oacc[i][2] = fmaf(tv, w4.z, oacc[i][2]);
                oacc[i][3] = fmaf(tv, w4.w, oacc[i][3]);
            }
        }
        __syncthreads();
    }
    float4 b24 = ((const float4*)b2)[lane];
    #pragma unroll
    for (int i = 0; i < 4; i++) {
        int n = nb + warp * 4 + i;
        if (n >= Nn) continue;
        float4 r4;
        r4.x = oacc[i][0] + hm[i].x + b24.x;
        r4.y = oacc[i][1] + hm[i].y + b24.y;
        r4.z = oacc[i][2] + hm[i].z + b24.z;
        r4.w = oacc[i][3] + hm[i].w + b24.w;
        ((float4*)(hout + (size_t)n * Ff))[lane] = r4;
    }
}

// ---------------- launcher ---------------------------------------------------------
extern "C" void kernel_launch(void* const* d_in, const int* in_sizes, int n_in,
                              void* d_out, int out_size) {
    const float* input     = (const float*)d_in[0];
    const float* cond      = (const float*)d_in[1];
    const float* a         = (const float*)d_in[2];
    const int*   batch     = (const int*)d_in[3];
    const int*   edges     = (const int*)d_in[4];
    const float* w_ada_mix = (const float*)d_in[5];
    const float* b_ada_mix = (const float*)d_in[6];
    const float* w_h       = (const float*)d_in[7];
    const float* b_h       = (const float*)d_in[8];
    const float* w_a       = (const float*)d_in[9];
    const float* w_vatt    = (const float*)d_in[10];
    const float* w_out     = (const float*)d_in[11];
    const float* b_out     = (const float*)d_in[12];
    const float* g_edge_p  = (const float*)d_in[13];
    const float* be_edge_p = (const float*)d_in[14];
    const float* w_edge    = (const float*)d_in[15];
    const float* b_edge    = (const float*)d_in[16];
    const float* w_ada_mlp = (const float*)d_in[17];
    const float* b_ada_mlp = (const float*)d_in[18];
    const float* w1        = (const float*)d_in[19];
    const float* b1        = (const float*)d_in[20];
    const float* w2        = (const float*)d_in[21];
    const float* b2        = (const float*)d_in[22];

    float* hout = (float*)d_out;                       // h: [N, F]
    float* aout = (float*)d_out + (size_t)Nn * Ff;     // a_out: [E, EF]

    const int SM_NODE1 = (Ff * F2 + TILE_N * 136) * 4;                              // 165888
    const int SM_EDGE  = (EFe * Ff + Ff * 224 + 2 * TILE_E * EFe + TILE_E * 136 + 3 * EFe) * 4
                       + TILE_E * 4;                                                // ~216 KB
    const int SM_N2M   = (Ff * Ff + 2 * TILE_N * 136) * 4;                          // 135168

    cudaFuncSetAttribute(k_node1,    cudaFuncAttributeMaxDynamicSharedMemorySize, SM_NODE1);
    cudaFuncSetAttribute(k_edge,     cudaFuncAttributeMaxDynamicSharedMemorySize, SM_EDGE);
    cudaFuncSetAttribute(k_node2mlp, cudaFuncAttributeMaxDynamicSharedMemorySize, SM_N2M);

    const int NT = (Nn + TILE_N - 1) / TILE_N;  // 313

    k_init<<<(Nn * Ff + 255) / 256, 256>>>();
    k_cond<<<dim3(Gg, 2), 256>>>(cond, w_ada_mix, b_ada_mix, w_ada_mlp, b_ada_mlp);
    k_node1<<<NT, 512, SM_NODE1>>>(input, batch, w_h, b_h);
    k_edge<<<296, 512, SM_EDGE>>>(a, edges, w_a, w_vatt, w_edge,
                                  g_edge_p, be_edge_p, b_edge, aout);
    k_node2mlp<<<NT, 512, SM_N2M>>>(input, batch, w_out, b_out, w1, b1, w2, b2, hout);
}

// round 6
// speedup vs baseline: 2.9229x; 1.8400x over previous
#include <cuda_runtime.h>
#include <cuda_bf16.h>
#include <cstdint>
#include <cstddef>

#define Nn 20000
#define Ee 320000
#define Ff 128
#define Hh 8
#define EFe 64
#define Aa 128
#define Gg 32
#define F2 256
#define TILE_N 64
#define ETILE 128
#define NTILES (Ee / ETILE)

// ---------------- scratch (device globals; no allocations allowed) ----------------
__device__ float g_sb_mix[Gg * F2];
__device__ float g_sb_mlp[Gg * F2];
__device__ float g_hsrc[(size_t)Nn * Ff];
__device__ float g_hdst[(size_t)Nn * Ff];
__device__ float g_wsum[Nn * Hh];
__device__ float g_o[(size_t)Nn * Ff];

__device__ __forceinline__ float siluf(float x) { return x / (1.f + __expf(-x)); }

// bf16 warp MMA: D[16x8] += A[16x16] * B[16x8], A row-major frags, B col-major frags
__device__ __forceinline__ void mma_bf16(float* d, uint32_t a0, uint32_t a1,
                                         uint32_t a2, uint32_t a3,
                                         uint32_t b0, uint32_t b1) {
    asm volatile(
        "mma.sync.aligned.m16n8k16.row.col.f32.bf16.bf16.f32 "
        "{%0,%1,%2,%3}, {%4,%5,%6,%7}, {%8,%9}, {%0,%1,%2,%3};"
        : "+f"(d[0]), "+f"(d[1]), "+f"(d[2]), "+f"(d[3])
        : "r"(a0), "r"(a1), "r"(a2), "r"(a3), "r"(b0), "r"(b1));
}

// ---------------- init: zero accumulators ----------------------------------------
__global__ void k_init() {
    int i = blockIdx.x * 256 + threadIdx.x;
    if (i < Nn * Ff) g_o[i] = 0.f;
    if (i < Nn * Hh) g_wsum[i] = 0.f;
}

// ---------------- cond GEMMs ------------------------------------------------------
__global__ __launch_bounds__(256) void k_cond(const float* __restrict__ cond,
                                              const float* __restrict__ w_mix,
                                              const float* __restrict__ b_mix,
                                              const float* __restrict__ w_mlp,
                                              const float* __restrict__ b_mlp) {
    __shared__ float cs[Aa];
    int g = blockIdx.x;
    int which = blockIdx.y;
    const float* w = which ? w_mlp : w_mix;
    const float* b = which ? b_mlp : b_mix;
    float* outp = which ? g_sb_mlp : g_sb_mix;
    int t = threadIdx.x;
    if (t < Aa) cs[t] = cond[g * Aa + t];
    __syncthreads();
    float acc = b[t];
    #pragma unroll 8
    for (int k = 0; k < Aa; k++) acc = fmaf(cs[k], w[k * F2 + t], acc);
    outp[g * F2 + t] = acc;
}

// ---------------- node kernel 1 (unchanged) ---------------------------------------
__global__ __launch_bounds__(512) void k_node1(const float* __restrict__ input,
                                               const int* __restrict__ batch,
                                               const float* __restrict__ w_h,
                                               const float* __restrict__ b_h) {
    extern __shared__ float sm[];
    float* w_s  = sm;
    float* xm_s = sm + Ff * F2;
    const int tid = threadIdx.x;
    const int warp = tid >> 5, lane = tid & 31;
    const int nb = blockIdx.x * TILE_N;

    {
        const float4* ws = (const float4*)w_h;
        float4* wd = (float4*)w_s;
        for (int i = tid; i < Ff * F2 / 4; i += 512) wd[i] = ws[i];
    }
    #pragma unroll
    for (int q = 0; q < 4; q++) {
        int r = warp * 4 + q;
        int n = nb + r;
        int nc = n < Nn ? n : Nn - 1;
        float4 x = ((const float4*)(input + (size_t)nc * Ff))[lane];
        float s  = x.x + x.y + x.z + x.w;
        float ss = fmaf(x.x, x.x, fmaf(x.y, x.y, fmaf(x.z, x.z, x.w * x.w)));
        #pragma unroll
        for (int o = 16; o > 0; o >>= 1) {
            s  += __shfl_xor_sync(0xffffffffu, s, o);
            ss += __shfl_xor_sync(0xffffffffu, ss, o);
        }
        float mu = s * (1.f / Ff);
        float rstd = rsqrtf(ss * (1.f / Ff) - mu * mu + 1e-5f);
        int bix = batch[nc];
        const float* sb = g_sb_mix + bix * F2;
        float4 sc = *((const float4*)(sb + lane * 4));
        float4 sh = *((const float4*)(sb + Ff + lane * 4));
        float4 o4;
        o4.x = (x.x - mu) * rstd * (1.f + sc.x) + sh.x;
        o4.y = (x.y - mu) * rstd * (1.f + sc.y) + sh.y;
        o4.z = (x.z - mu) * rstd * (1.f + sc.z) + sh.z;
        o4.w = (x.w - mu) * rstd * (1.f + sc.w) + sh.w;
        ((float4*)(xm_s + r * 136))[lane] = o4;
    }
    __syncthreads();

    float acc[4][8];
    #pragma unroll
    for (int i = 0; i < 4; i++)
        #pragma unroll
        for (int j = 0; j < 8; j++) acc[i][j] = 0.f;

    #pragma unroll 4
    for (int k = 0; k < Ff; k++) {
        float xa[4];
        #pragma unroll
        for (int i = 0; i < 4; i++) xa[i] = xm_s[(warp * 4 + i) * 136 + k];
        #pragma unroll
        for (int j = 0; j < 8; j++) {
            float wv = w_s[k * F2 + lane + 32 * j];
            #pragma unroll
            for (int i = 0; i < 4; i++) acc[i][j] = fmaf(xa[i], wv, acc[i][j]);
        }
    }
    #pragma unroll
    for (int j = 0; j < 8; j++) {
        int c = lane + 32 * j;
        float bb = __ldg(b_h + c);
        #pragma unroll
        for (int i = 0; i < 4; i++) {
            int n = nb + warp * 4 + i;
            if (n < Nn) {
                float v = acc[i][j] + bb;
                if (c < Ff) g_hsrc[(size_t)n * Ff + c] = v;
                else        g_hdst[(size_t)n * Ff + (c - Ff)] = v;
            }
        }
    }
}

// ========================= mma.sync bf16 edge kernel ===============================
// SMEM layout (bytes):
#define STRA 144             // row stride for 64-k bf16 tiles (an, w_aT)
#define STRB 272             // row stride for 128-k bf16 tiles (m, wcT)
#define OFF_WAT  0                           // w_a^T  [128n][64k]   18432
#define OFF_WCT  18432                       // wc^T   [224n][128k]  60928
#define OFF_AN   79360                       // an     [128m][64k]   18432
#define OFF_M    97792                       // m      [128m][128k]  34816
#define OFF_WEXP 132608                      // f32 [128][9]          4608
#define OFF_SRC  137216                      // int [128]
#define OFF_DST  137728                      // int [128]
#define OFF_GE   138240
#define OFF_BE   138496
#define OFF_BD   138752
#define SMEDGE   139008

__global__ __launch_bounds__(512) void k_edge(const float* __restrict__ ain,
                                              const int* __restrict__ edges,
                                              const float* __restrict__ w_a,
                                              const float* __restrict__ w_vatt,
                                              const float* __restrict__ w_edge,
                                              const float* __restrict__ gain_e,
                                              const float* __restrict__ bias_e,
                                              const float* __restrict__ b_edge,
                                              float* __restrict__ aout) {
    extern __shared__ __align__(16) char smem_raw[];
    const int tid = threadIdx.x;
    const int warp = tid >> 5, lane = tid & 31;
    const int g = lane >> 2, tg = lane & 3;
    const int wr = warp & 7;       // M-block (16 rows)
    const int wc = warp >> 3;      // N-group

    float* wexp_s = (float*)(smem_raw + OFF_WEXP);
    int*   src_s  = (int*)(smem_raw + OFF_SRC);
    int*   dst_s  = (int*)(smem_raw + OFF_DST);
    float* ge_s   = (float*)(smem_raw + OFF_GE);
    float* be_s   = (float*)(smem_raw + OFF_BE);
    float* bd_s   = (float*)(smem_raw + OFF_BD);

    // ---- one-time weight staging ----
    // w_aT[n][k] = w_a[k][n]
    for (int i = tid; i < 128 * 64; i += 512) {
        int n = i >> 6, k = i & 63;
        *(__nv_bfloat16*)(smem_raw + OFF_WAT + n * STRA + k * 2) =
            __float2bfloat16(w_a[k * Ff + n]);
    }
    // wcT[n][k]: n<136 -> w_vatt, 136<=n<200 -> w_edge, else 0
    for (int i = tid; i < 224 * 128; i += 512) {
        int n = i >> 7, k = i & 127;
        float v = 0.f;
        if (n < 136)               v = w_vatt[k * 136 + n];
        else if (n < 200)          v = w_edge[k * EFe + (n - 136)];
        *(__nv_bfloat16*)(smem_raw + OFF_WCT + n * STRB + k * 2) = __float2bfloat16(v);
    }
    if (tid < EFe) { ge_s[tid] = gain_e[tid]; be_s[tid] = bias_e[tid]; bd_s[tid] = b_edge[tid]; }
    __syncthreads();

    for (int tile = blockIdx.x; tile < NTILES; tile += gridDim.x) {
        const int e0 = tile * ETILE;

        if (tid < ETILE) {
            src_s[tid] = edges[e0 + tid];
            dst_s[tid] = edges[Ee + e0 + tid];
        }

        // ---- LN(a) -> an (bf16). Each warp: 8 rows ----
        #pragma unroll
        for (int q = 0; q < 8; q++) {
            int r = warp * 8 + q;
            const float* arow = ain + (size_t)(e0 + r) * EFe;
            float x0 = __ldg(arow + lane);
            float x1 = __ldg(arow + lane + 32);
            float s = x0 + x1;
            float ss = fmaf(x0, x0, x1 * x1);
            #pragma unroll
            for (int o = 16; o > 0; o >>= 1) {
                s  += __shfl_xor_sync(0xffffffffu, s, o);
                ss += __shfl_xor_sync(0xffffffffu, ss, o);
            }
            float mu = s * (1.f / EFe);
            float rstd = rsqrtf(ss * (1.f / EFe) - mu * mu + 1e-5f);
            float v0 = (x0 - mu) * rstd * ge_s[lane]      + be_s[lane];
            float v1 = (x1 - mu) * rstd * ge_s[lane + 32] + be_s[lane + 32];
            *(__nv_bfloat16*)(smem_raw + OFF_AN + r * STRA + lane * 2)        = __float2bfloat16(v0);
            *(__nv_bfloat16*)(smem_raw + OFF_AN + r * STRA + (lane + 32) * 2) = __float2bfloat16(v1);
        }
        __syncthreads();

        const int row0 = wr * 16 + g, row1 = row0 + 8;
        const int s0 = src_s[row0], s1 = src_s[row1];

        // ---- GEMM1: D1[128,128] = an[128,64] @ w_a[64,128] ----
        float d1[8][4];
        #pragma unroll
        for (int i = 0; i < 8; i++) { d1[i][0]=0.f; d1[i][1]=0.f; d1[i][2]=0.f; d1[i][3]=0.f; }
        {
            const char* anp = smem_raw + OFF_AN;
            const char* wap = smem_raw + OFF_WAT;
            #pragma unroll
            for (int ks = 0; ks < 4; ks++) {
                int k0 = ks * 16;
                uint32_t a0 = *(const uint32_t*)(anp + row0 * STRA + (k0 + 2 * tg) * 2);
                uint32_t a1 = *(const uint32_t*)(anp + row1 * STRA + (k0 + 2 * tg) * 2);
                uint32_t a2 = *(const uint32_t*)(anp + row0 * STRA + (k0 + 2 * tg + 8) * 2);
                uint32_t a3 = *(const uint32_t*)(anp + row1 * STRA + (k0 + 2 * tg + 8) * 2);
                #pragma unroll
                for (int nb = 0; nb < 8; nb++) {
                    int n0 = wc * 64 + nb * 8;
                    uint32_t b0 = *(const uint32_t*)(wap + (n0 + g) * STRA + (k0 + 2 * tg) * 2);
                    uint32_t b1 = *(const uint32_t*)(wap + (n0 + g) * STRA + (k0 + 2 * tg + 8) * 2);
                    mma_bf16(d1[nb], a0, a1, a2, a3, b0, b1);
                }
            }
        }

        // ---- epilogue 1: m = silu(D1 + hsrc[src] + hdst[dst]) -> m_s (bf16) ----
        {
            const int dd0 = dst_s[row0], dd1 = dst_s[row1];
            #pragma unroll
            for (int nb = 0; nb < 8; nb++) {
                int col = wc * 64 + nb * 8 + 2 * tg;
                float2 hs0 = *(const float2*)(g_hsrc + (size_t)s0 * Ff + col);
                float2 hd0 = *(const float2*)(g_hdst + (size_t)dd0 * Ff + col);
                float2 hs1 = *(const float2*)(g_hsrc + (size_t)s1 * Ff + col);
                float2 hd1 = *(const float2*)(g_hdst + (size_t)dd1 * Ff + col);
                float m00 = siluf(d1[nb][0] + hs0.x + hd0.x);
                float m01 = siluf(d1[nb][1] + hs0.y + hd0.y);
                float m10 = siluf(d1[nb][2] + hs1.x + hd1.x);
                float m11 = siluf(d1[nb][3] + hs1.y + hd1.y);
                __nv_bfloat162 p0 = __floats2bfloat162_rn(m00, m01);
                __nv_bfloat162 p1 = __floats2bfloat162_rn(m10, m11);
                *(uint32_t*)(smem_raw + OFF_M + row0 * STRB + col * 2) = *(uint32_t*)&p0;
                *(uint32_t*)(smem_raw + OFF_M + row1 * STRB + col * 2) = *(uint32_t*)&p1;
            }
        }
        __syncthreads();

        // ---- GEMM2: D2[128,224] = m[128,128] @ wc[128,224] ----
        float d2[14][4];
        #pragma unroll
        for (int i = 0; i < 14; i++) { d2[i][0]=0.f; d2[i][1]=0.f; d2[i][2]=0.f; d2[i][3]=0.f; }
        {
            const char* mp  = smem_raw + OFF_M;
            const char* wcp = smem_raw + OFF_WCT;
            #pragma unroll
            for (int ks = 0; ks < 8; ks++) {
                int k0 = ks * 16;
                uint32_t a0 = *(const uint32_t*)(mp + row0 * STRB + (k0 + 2 * tg) * 2);
                uint32_t a1 = *(const uint32_t*)(mp + row1 * STRB + (k0 + 2 * tg) * 2);
                uint32_t a2 = *(const uint32_t*)(mp + row0 * STRB + (k0 + 2 * tg + 8) * 2);
                uint32_t a3 = *(const uint32_t*)(mp + row1 * STRB + (k0 + 2 * tg + 8) * 2);
                #pragma unroll
                for (int nb = 0; nb < 14; nb++) {
                    int n0 = wc * 112 + nb * 8;
                    uint32_t b0 = *(const uint32_t*)(wcp + (n0 + g) * STRB + (k0 + 2 * tg) * 2);
                    uint32_t b1 = *(const uint32_t*)(wcp + (n0 + g) * STRB + (k0 + 2 * tg + 8) * 2);
                    mma_bf16(d2[nb], a0, a1, a2, a3, b0, b1);
                }
            }
        }

        // ---- epilogue 2 ----
        // head logits: cols 128..135 = (wc==1, nb==2)
        if (wc == 1) {
            int h = 2 * tg;
            float e00 = __expf(d2[2][0]);
            float e01 = __expf(d2[2][1]);
            float e10 = __expf(d2[2][2]);
            float e11 = __expf(d2[2][3]);
            wexp_s[row0 * 9 + h]     = e00;
            wexp_s[row0 * 9 + h + 1] = e01;
            wexp_s[row1 * 9 + h]     = e10;
            wexp_s[row1 * 9 + h + 1] = e11;
            float* p0 = g_wsum + (size_t)s0 * Hh + h;
            float* p1 = g_wsum + (size_t)s1 * Hh + h;
            asm volatile("red.global.add.f32 [%0], %1;" :: "l"(p0),     "f"(e00) : "memory");
            asm volatile("red.global.add.f32 [%0], %1;" :: "l"(p0 + 1), "f"(e01) : "memory");
            asm volatile("red.global.add.f32 [%0], %1;" :: "l"(p1),     "f"(e10) : "memory");
            asm volatile("red.global.add.f32 [%0], %1;" :: "l"(p1 + 1), "f"(e11) : "memory");
        }
        __syncthreads();

        #pragma unroll
        for (int nb = 0; nb < 14; nb++) {
            int col = wc * 112 + nb * 8 + 2 * tg;
            if (col < Ff) {
                int h = col >> 4;
                float w0 = wexp_s[row0 * 9 + h];
                float w1 = wexp_s[row1 * 9 + h];
                float* o0 = g_o + (size_t)s0 * Ff + col;
                float* o1 = g_o + (size_t)s1 * Ff + col;
                asm volatile("red.global.add.v2.f32 [%0], {%1, %2};"
                             :: "l"(o0), "f"(d2[nb][0] * w0), "f"(d2[nb][1] * w0) : "memory");
                asm volatile("red.global.add.v2.f32 [%0], {%1, %2};"
                             :: "l"(o1), "f"(d2[nb][2] * w1), "f"(d2[nb][3] * w1) : "memory");
            } else if (col >= 136 && col < 200) {
                int k2 = col - 136;
                float2 a0v = *(const float2*)(ain + (size_t)(e0 + row0) * EFe + k2);
                float2 a1v = *(const float2*)(ain + (size_t)(e0 + row1) * EFe + k2);
                float2 r0v, r1v;
                r0v.x = a0v.x + d2[nb][0] + bd_s[k2];
                r0v.y = a0v.y + d2[nb][1] + bd_s[k2 + 1];
                r1v.x = a1v.x + d2[nb][2] + bd_s[k2];
                r1v.y = a1v.y + d2[nb][3] + bd_s[k2 + 1];
                *(float2*)(aout + (size_t)(e0 + row0) * EFe + k2) = r0v;
                *(float2*)(aout + (size_t)(e0 + row1) * EFe + k2) = r1v;
            }
        }
        __syncthreads();   // protect src_s/dst_s/an/m for next tile
    }
}

// ------- fused node kernel 2 + MLP (unchanged from round 3) ------------------------
__global__ __launch_bounds__(512) void k_node2mlp(const float* __restrict__ input,
                                                  const int* __restrict__ batch,
                                                  const float* __restrict__ w_out,
                                                  const float* __restrict__ b_out,
                                                  const float* __restrict__ w1,
                                                  const float* __restrict__ b1,
                                                  const float* __restrict__ w2,
                                                  const float* __restrict__ b2,
                                                  float* __restrict__ hout) {
    extern __shared__ float sm[];
    float* w_s  = sm;
    float* xn_s = sm + Ff * Ff;
    float* t_s  = xn_s + TILE_N * 136;
    const int tid = threadIdx.x;
    const int warp = tid >> 5, lane = tid & 31;
    const int nb = blockIdx.x * TILE_N;

    {
        const float4* ws = (const float4*)w_out;
        float4* wd = (float4*)w_s;
        for (int i = tid; i < Ff * Ff / 4; i += 512) wd[i] = ws[i];
    }
    for (int i = tid; i < TILE_N * Ff / 4; i += 512) {
        int r = i >> 5, c4 = i & 31;
        int n = nb + r;
        int nc = n < Nn ? n : Nn - 1;
        float4 o4 = ((const float4*)(g_o + (size_t)nc * Ff))[c4];
        int h = c4 >> 2;
        float inv = 1.f / (g_wsum[nc * Hh + h] + 1e-16f);
        o4.x *= inv; o4.y *= inv; o4.z *= inv; o4.w *= inv;
        ((float4*)(t_s + r * 136))[c4] = o4;
    }
    __syncthreads();

    float acc[4][4];
    #pragma unroll
    for (int i = 0; i < 4; i++) { acc[i][0]=0.f; acc[i][1]=0.f; acc[i][2]=0.f; acc[i][3]=0.f; }
    #pragma unroll 4
    for (int k = 0; k < Ff; k++) {
        float4 w4 = ((const float4*)(w_s + k * Ff))[lane];
        #pragma unroll
        for (int i = 0; i < 4; i++) {
            float ov = t_s[(warp * 4 + i) * 136 + k];
            acc[i][0] = fmaf(ov, w4.x, acc[i][0]);
            acc[i][1] = fmaf(ov, w4.y, acc[i][1]);
            acc[i][2] = fmaf(ov, w4.z, acc[i][2]);
            acc[i][3] = fmaf(ov, w4.w, acc[i][3]);
        }
    }
    float4 hm[4];
    {
        float4 b4 = ((const float4*)b_out)[lane];
        #pragma unroll
        for (int i = 0; i < 4; i++) {
            int n = nb + warp * 4 + i;
            int nc = n < Nn ? n : Nn - 1;
            float4 in4 = ((const float4*)(input + (size_t)nc * Ff))[lane];
            hm[i].x = acc[i][0] + in4.x + b4.x;
            hm[i].y = acc[i][1] + in4.y + b4.y;
            hm[i].z = acc[i][2] + in4.z + b4.z;
            hm[i].w = acc[i][3] + in4.w + b4.w;
        }
    }

    #pragma unroll
    for (int q = 0; q < 4; q++) {
        int r = warp * 4 + q;
        int n = nb + r;
        int nc = n < Nn ? n : Nn - 1;
        float4 x = hm[q];
        float s  = x.x + x.y + x.z + x.w;
        float ss = fmaf(x.x, x.x, fmaf(x.y, x.y, fmaf(x.z, x.z, x.w * x.w)));
        #pragma unroll
        for (int o = 16; o > 0; o >>= 1) {
            s  += __shfl_xor_sync(0xffffffffu, s, o);
            ss += __shfl_xor_sync(0xffffffffu, ss, o);
        }
        float mu = s * (1.f / Ff);
        float rstd = rsqrtf(ss * (1.f / Ff) - mu * mu + 1e-5f);
        int bix = batch[nc];
        const float* sb = g_sb_mlp + bix * F2;
        float4 sc = *((const float4*)(sb + lane * 4));
        float4 sh = *((const float4*)(sb + Ff + lane * 4));
        float4 o4;
        o4.x = (x.x - mu) * rstd * (1.f + sc.x) + sh.x;
        o4.y = (x.y - mu) * rstd * (1.f + sc.y) + sh.y;
        o4.z = (x.z - mu) * rstd * (1.f + sc.z) + sh.z;
        o4.w = (x.w - mu) * rstd * (1.f + sc.w) + sh.w;
        ((float4*)(xn_s + r * 136))[lane] = o4;
    }
    __syncthreads();

    float oacc[4][4];
    #pragma unroll
    for (int i = 0; i < 4; i++) { oacc[i][0]=0.f; oacc[i][1]=0.f; oacc[i][2]=0.f; oacc[i][3]=0.f; }

    for (int ch = 0; ch < 4; ch++) {
        for (int i = tid; i < Ff * Ff; i += 512) {
            int k = i >> 7, c = i & 127;
            w_s[i] = w1[k * 512 + ch * 128 + c];
        }
        __syncthreads();
        float acc2[4][4];
        #pragma unroll
        for (int i = 0; i < 4; i++) { acc2[i][0]=0.f; acc2[i][1]=0.f; acc2[i][2]=0.f; acc2[i][3]=0.f; }
        #pragma unroll 4
        for (int k = 0; k < Ff; k++) {
            float4 w4 = ((const float4*)(w_s + k * Ff))[lane];
            #pragma unroll
            for (int i = 0; i < 4; i++) {
                float xv = xn_s[(warp * 4 + i) * 136 + k];
                acc2[i][0] = fmaf(xv, w4.x, acc2[i][0]);
                acc2[i][1] = fmaf(xv, w4.y, acc2[i][1]);
                acc2[i][2] = fmaf(xv, w4.z, acc2[i][2]);
                acc2[i][3] = fmaf(xv, w4.w, acc2[i][3]);
            }
        }
        float4 b14 = ((const float4*)b1)[ch * 32 + lane];
        #pragma unroll
        for (int i = 0; i < 4; i++) {
            int r = warp * 4 + i;
            float4 t4;
            t4.x = siluf(acc2[i][0] + b14.x);
            t4.y = siluf(acc2[i][1] + b14.y);
            t4.z = siluf(acc2[i][2] + b14.z);
            t4.w = siluf(acc2[i][3] + b14.w);
            ((float4*)(t_s + r * 136))[lane] = t4;
        }
        __syncthreads();
        {
            const float4* ws = (const float4*)(w2 + (size_t)ch * Ff * Ff);
            float4* wd = (float4*)w_s;
            for (int i = tid; i < Ff * Ff / 4; i += 512) wd[i] = ws[i];
        }
        __syncthreads();
        #pragma unroll 4
        for (int k = 0; k < Ff; k++) {
            float4 w4 = ((const float4*)(w_s + k * Ff))[lane];
            #pragma unroll
            for (int i = 0; i < 4; i++) {
                float tv = t_s[(warp * 4 + i) * 136 + k];
                oacc[i][0] = fmaf(tv, w4.x, oacc[i][0]);
                oacc[i][1] = fmaf(tv, w4.y, oacc[i][1]);
                oacc[i][2] = fmaf(tv, w4.z, oacc[i][2]);
                oacc[i][3] = fmaf(tv, w4.w, oacc[i][3]);
            }
        }
        __syncthreads();
    }
    float4 b24 = ((const float4*)b2)[lane];
    #pragma unroll
    for (int i = 0; i < 4; i++) {
        int n = nb + warp * 4 + i;
        if (n >= Nn) continue;
        float4 r4;
        r4.x = oacc[i][0] + hm[i].x + b24.x;
        r4.y = oacc[i][1] + hm[i].y + b24.y;
        r4.z = oacc[i][2] + hm[i].z + b24.z;
        r4.w = oacc[i][3] + hm[i].w + b24.w;
        ((float4*)(hout + (size_t)n * Ff))[lane] = r4;
    }
}

// ---------------- launcher ---------------------------------------------------------
extern "C" void kernel_launch(void* const* d_in, const int* in_sizes, int n_in,
                              void* d_out, int out_size) {
    const float* input     = (const float*)d_in[0];
    const float* cond      = (const float*)d_in[1];
    const float* a         = (const float*)d_in[2];
    const int*   batch     = (const int*)d_in[3];
    const int*   edges     = (const int*)d_in[4];
    const float* w_ada_mix = (const float*)d_in[5];
    const float* b_ada_mix = (const float*)d_in[6];
    const float* w_h       = (const float*)d_in[7];
    const float* b_h       = (const float*)d_in[8];
    const float* w_a       = (const float*)d_in[9];
    const float* w_vatt    = (const float*)d_in[10];
    const float* w_out     = (const float*)d_in[11];
    const float* b_out     = (const float*)d_in[12];
    const float* g_edge_p  = (const float*)d_in[13];
    const float* be_edge_p = (const float*)d_in[14];
    const float* w_edge    = (const float*)d_in[15];
    const float* b_edge    = (const float*)d_in[16];
    const float* w_ada_mlp = (const float*)d_in[17];
    const float* b_ada_mlp = (const float*)d_in[18];
    const float* w1        = (const float*)d_in[19];
    const float* b1        = (const float*)d_in[20];
    const float* w2        = (const float*)d_in[21];
    const float* b2        = (const float*)d_in[22];

    float* hout = (float*)d_out;                       // h: [N, F]
    float* aout = (float*)d_out + (size_t)Nn * Ff;     // a_out: [E, EF]

    const int SM_NODE1 = (Ff * F2 + TILE_N * 136) * 4;     // 165888
    const int SM_N2M   = (Ff * Ff + 2 * TILE_N * 136) * 4; // 135168

    cudaFuncSetAttribute(k_node1,    cudaFuncAttributeMaxDynamicSharedMemorySize, SM_NODE1);
    cudaFuncSetAttribute(k_edge,     cudaFuncAttributeMaxDynamicSharedMemorySize, SMEDGE);
    cudaFuncSetAttribute(k_node2mlp, cudaFuncAttributeMaxDynamicSharedMemorySize, SM_N2M);

    const int NT = (Nn + TILE_N - 1) / TILE_N;  // 313

    k_init<<<(Nn * Ff + 255) / 256, 256>>>();
    k_cond<<<dim3(Gg, 2), 256>>>(cond, w_ada_mix, b_ada_mix, w_ada_mlp, b_ada_mlp);
    k_node1<<<NT, 512, SM_NODE1>>>(input, batch, w_h, b_h);
    k_edge<<<148, 512, SMEDGE>>>(a, edges, w_a, w_vatt, w_edge,
                                 g_edge_p, be_edge_p, b_edge, aout);
    k_node2mlp<<<NT, 512, SM_N2M>>>(input, batch, w_out, b_out, w1, b1, w2, b2, hout);
}